// round 7
// baseline (speedup 1.0000x reference)
#include <cuda_runtime.h>
#include <cuda_fp16.h>
#include <math.h>
#include <cstdint>

#define B_   8
#define T_   1024
#define C_   1024
#define H_   16
#define DH   64
#define M_   (B_*T_)
#define KDIM 1024
#define EPS_ 1e-5f

// ---------------- scratch (device globals) ----------------
__device__ __half g_xnh  [M_*C_];
__device__ __half g_qkvh [3ll*M_*C_];      // q,k: [B,H,T,Dh]; v: [B,H,Dh,T]
__device__ __half g_attnh[M_*C_];
__device__ __half g_h1h  [M_*C_];
__device__ float  g_x1   [M_*C_];
__device__ __half g_wqkvh[3ll*C_*C_];      // [N=3072][K=1024]
__device__ __half g_wpth [C_*C_];
__device__ __half g_w1th [C_*C_];
__device__ __half g_w2th [C_*C_];

// ================= helpers =================
__device__ __forceinline__ uint32_t smem_u32(const void* p) {
    uint32_t a;
    asm("{ .reg .u64 t; cvta.to.shared.u64 t, %1; cvt.u32.u64 %0, t; }" : "=r"(a) : "l"(p));
    return a;
}
__device__ __forceinline__ void cp_async16(uint32_t dst, const void* src) {
    asm volatile("cp.async.cg.shared.global [%0], [%1], 16;" :: "r"(dst), "l"(src));
}
#define CP_COMMIT() asm volatile("cp.async.commit_group;" ::: "memory")
#define CP_WAIT(n)  asm volatile("cp.async.wait_group %0;" :: "n"(n) : "memory")

__device__ __forceinline__ void mma_f16(float* d, const uint32_t* a, const uint32_t* b) {
    asm volatile(
        "mma.sync.aligned.m16n8k16.row.col.f32.f16.f16.f32 "
        "{%0,%1,%2,%3}, {%4,%5,%6,%7}, {%8,%9}, {%0,%1,%2,%3};"
        : "+f"(d[0]), "+f"(d[1]), "+f"(d[2]), "+f"(d[3])
        : "r"(a[0]), "r"(a[1]), "r"(a[2]), "r"(a[3]), "r"(b[0]), "r"(b[1]));
}
__device__ __forceinline__ void ldsm_x4(uint32_t* r, uint32_t addr) {
    asm volatile("ldmatrix.sync.aligned.m8n8.x4.shared.b16 {%0,%1,%2,%3}, [%4];"
        : "=r"(r[0]), "=r"(r[1]), "=r"(r[2]), "=r"(r[3]) : "r"(addr));
}

// ================= weight transposes (fp32 -> fp16 [N][K]) ============
__global__ void __launch_bounds__(256) transpose_kernel(const float* __restrict__ in,
                                                        __half* __restrict__ out)
{
    __shared__ float tile[32][33];
    int tx = threadIdx.x, ty = threadIdx.y;
    int n0 = blockIdx.x * 32, k0 = blockIdx.y * 32;
    #pragma unroll
    for (int i = 0; i < 32; i += 8)
        tile[ty + i][tx] = in[(size_t)(k0 + ty + i) * C_ + n0 + tx];
    __syncthreads();
    #pragma unroll
    for (int i = 0; i < 32; i += 8)
        out[(size_t)(n0 + ty + i) * KDIM + k0 + tx] = __float2half_rn(tile[tx][ty + i]);
}

__global__ void __launch_bounds__(256) transpose_qkv_kernel(const float* __restrict__ in,
                                                            __half* __restrict__ out)
{
    __shared__ float tile[32][33];
    int tx = threadIdx.x, ty = threadIdx.y;
    int h = blockIdx.z;
    int d0 = blockIdx.x * 32, c0 = blockIdx.y * 32;
    #pragma unroll
    for (int i = 0; i < 32; i += 8)
        tile[ty + i][tx] = in[(size_t)h * (C_ * DH) + (size_t)(c0 + ty + i) * DH + d0 + tx];
    __syncthreads();
    #pragma unroll
    for (int i = 0; i < 32; i += 8)
        out[(size_t)(h * DH + d0 + ty + i) * KDIM + c0 + tx] = __float2half_rn(tile[tx][ty + i]);
}

// ================= fp16 GEMM: 128x256 tile, 512 thr, BK=64h, 3-stage =============
enum { EPI_QKV = 0, EPI_PROJ = 1, EPI_RELU = 2, EPI_RESID = 3 };

#define BM 128
#define BN 256
#define BKH 64
#define NCHUNK (KDIM / BKH)                // 16
#define A_H (BM*BKH)                       // 8192 halves
#define B_H (BN*BKH)                       // 16384
#define STG_H (A_H + B_H)                  // 24576 halves (48KB)
#define SMEM_SZ (3 * STG_H * 2)            // 147456 B

// swizzled half-index within a row-major [rows][64h] tile
__device__ __forceinline__ int hidx(int row, int grp, int off) {
    return row * 64 + ((grp ^ (row & 7)) << 3) + off;
}

template<int EPI>
__global__ void __launch_bounds__(512) mma_gemm(
    const __half* __restrict__ A,      // [M][1024]
    const __half* __restrict__ Bt,     // [Ntot][1024]
    const float*  __restrict__ bias,
    const float*  __restrict__ resid,
    void*         __restrict__ outv)
{
    extern __shared__ __half sm[];
    int tid = threadIdx.x, wid = tid >> 5, lane = tid & 31;
    int warpM = wid & 3, warpN = wid >> 2;      // 4 x 4 warps
    int qrow = lane >> 2, qc = lane & 3;
    int lrow = lane & 15, gh = lane >> 4;       // ldmatrix row / k-half
    int mBase = blockIdx.y * BM, nBase = blockIdx.x * BN;

    const __half* aSrc = A  + (size_t)mBase * KDIM;
    const __half* bSrc = Bt + (size_t)nBase * KDIM;

    auto load_stage = [&](int c, int s) {
        __half* dA = sm + s * STG_H;
        __half* dB = dA + A_H;
        #pragma unroll
        for (int i = 0; i < 2; i++) {
            int id = tid + i * 512, r = id >> 3, g = id & 7;
            cp_async16(smem_u32(dA + hidx(r, g, 0)),
                       aSrc + (size_t)r * KDIM + c * BKH + g * 8);
        }
        #pragma unroll
        for (int i = 0; i < 4; i++) {
            int id = tid + i * 512, r = id >> 3, g = id & 7;
            cp_async16(smem_u32(dB + hidx(r, g, 0)),
                       bSrc + (size_t)r * KDIM + c * BKH + g * 8);
        }
    };

    // per-lane ldmatrix row bases (bytes within tile) + row&7 for swizzle
    int rA[2], rB[4];
    rA[0] = warpM * 32 + lrow;  rA[1] = rA[0] + 16;
    #pragma unroll
    for (int p = 0; p < 4; p++) rB[p] = warpN * 64 + p * 16 + lrow;

    float acc[2][8][4];
    #pragma unroll
    for (int mt = 0; mt < 2; mt++)
        #pragma unroll
        for (int nt = 0; nt < 8; nt++)
            #pragma unroll
            for (int r = 0; r < 4; r++) acc[mt][nt][r] = 0.f;

    load_stage(0, 0); CP_COMMIT();
    load_stage(1, 1); CP_COMMIT();

    uint32_t smBase = smem_u32(sm);

    #pragma unroll 1
    for (int c = 0; c < NCHUNK; c++) {
        if (c < NCHUNK - 2) { CP_WAIT(1); } else { CP_WAIT(0); }
        __syncthreads();
        if (c + 2 < NCHUNK) { load_stage(c + 2, (c + 2) % 3); CP_COMMIT(); }

        uint32_t baseA = smBase + (c % 3) * (STG_H * 2);
        uint32_t baseB = baseA + A_H * 2;

        #pragma unroll
        for (int ks = 0; ks < 4; ks++) {
            int grp = 2 * ks + gh;
            uint32_t af[2][4];
            ldsm_x4(af[0], baseA + (rA[0] * 64 + ((grp ^ (rA[0] & 7)) << 3)) * 2);
            ldsm_x4(af[1], baseA + (rA[1] * 64 + ((grp ^ (rA[1] & 7)) << 3)) * 2);
            #pragma unroll
            for (int p = 0; p < 4; p++) {
                uint32_t bf[4];
                ldsm_x4(bf, baseB + (rB[p] * 64 + ((grp ^ (rB[p] & 7)) << 3)) * 2);
                uint32_t b0[2] = { bf[0], bf[2] }, b1[2] = { bf[1], bf[3] };
                mma_f16(acc[0][2*p],   af[0], b0);
                mma_f16(acc[1][2*p],   af[1], b0);
                mma_f16(acc[0][2*p+1], af[0], b1);
                mma_f16(acc[1][2*p+1], af[1], b1);
            }
        }
    }

    // ---- epilogue ----
    #pragma unroll
    for (int mt = 0; mt < 2; mt++) {
        #pragma unroll
        for (int r = 0; r < 2; r++) {
            int m = mBase + warpM * 32 + mt * 16 + qrow + r * 8;
            #pragma unroll
            for (int nt = 0; nt < 8; nt++) {
                int col = nBase + warpN * 64 + nt * 8 + qc * 2;
                float vx = acc[mt][nt][r * 2], vy = acc[mt][nt][r * 2 + 1];
                if (EPI == EPI_QKV) {
                    __half* out = (__half*)outv;
                    int which = col >> 10, nn = col & 1023;
                    int h = nn >> 6, d = nn & 63;
                    int b = m >> 10, t = m & 1023;
                    if (which == 0) {
                        *reinterpret_cast<__half2*>(
                            &out[((size_t)(b * H_ + h) * T_ + t) * DH + d]) =
                            __floats2half2_rn(vx * 0.125f, vy * 0.125f);
                    } else if (which == 1) {
                        *reinterpret_cast<__half2*>(
                            &out[(size_t)M_ * C_ + ((size_t)(b * H_ + h) * T_ + t) * DH + d]) =
                            __floats2half2_rn(vx, vy);
                    } else {
                        size_t vbase = 2ll * M_ * C_;
                        size_t hd    = (size_t)(b * H_ + h) * DH;
                        out[vbase + (hd + d)     * T_ + t] = __float2half_rn(vx);
                        out[vbase + (hd + d + 1) * T_ + t] = __float2half_rn(vy);
                    }
                } else if (EPI == EPI_RELU) {
                    __half* out = (__half*)outv;
                    size_t idx = (size_t)m * C_ + col;
                    float ox = fmaxf(vx + bias[col], 0.f);
                    float oy = fmaxf(vy + bias[col + 1], 0.f);
                    *reinterpret_cast<__half2*>(&out[idx]) = __floats2half2_rn(ox, oy);
                } else {
                    float* out = (float*)outv;
                    size_t idx = (size_t)m * C_ + col;
                    float2 rs = *reinterpret_cast<const float2*>(&resid[idx]);
                    float2 o = { vx + bias[col] + rs.x, vy + bias[col + 1] + rs.y };
                    *reinterpret_cast<float2*>(&out[idx]) = o;
                }
            }
        }
    }
}

// ================= fused flash attention (fp16 mma + ldmatrix) ===============
#define FQ 0
#define FK 9216
#define FV 18432
#define FP 27136
#define FA_HALVES (27136 + 17408)
#define FA_SMEM (FA_HALVES * 2)            // 89088 bytes

__global__ void __launch_bounds__(256) flash_kernel()
{
    extern __shared__ __half fs[];
    int tid = threadIdx.x, wid = tid >> 5, lane = tid & 31;
    int qrow = lane >> 2, qc = lane & 3;
    int lrow = lane & 15, gh = lane >> 4;
    int qt = gridDim.x - 1 - blockIdx.x;
    int bh = blockIdx.y;

    const __half* Q  = g_qkvh + ((size_t)bh * T_ + qt * 128) * DH;
    const __half* K  = g_qkvh + (size_t)M_ * C_  + (size_t)bh * T_ * DH;
    const __half* Vt = g_qkvh + 2ll * M_ * C_    + (size_t)bh * DH * T_;   // [Dh][T]

    auto ld_qk = [&](__half* dst, const __half* src) {
        #pragma unroll
        for (int i = 0; i < 4; i++) {
            int id = tid + i * 256;
            int row = id >> 3, j = id & 7;
            cp_async16(smem_u32(dst + row * 72 + j * 8), src + row * 64 + j * 8);
        }
    };
    auto ld_v = [&](__half* dst, const __half* src, int kt) {
        #pragma unroll
        for (int i = 0; i < 4; i++) {
            int id = tid + i * 256;
            int row = id >> 4, j = id & 15;
            cp_async16(smem_u32(dst + row * 136 + j * 8),
                       src + (size_t)row * T_ + kt * 128 + j * 8);
        }
    };

    ld_qk(fs + FQ, Q);
    CP_COMMIT();

    int rowA = wid * 16 + qrow;
    int lmRow = wid * 16 + lrow;                 // ldmatrix row for this warp's tiles
    uint32_t fsb = smem_u32(fs);

    float m[2] = { -1e30f, -1e30f }, l[2] = { 0.f, 0.f };
    float o[8][4];
    #pragma unroll
    for (int nt = 0; nt < 8; nt++)
        #pragma unroll
        for (int r = 0; r < 4; r++) o[nt][r] = 0.f;

    __half* Ps = fs + FP;
    uint32_t qf[4][4];                            // hoisted Q fragments

    #pragma unroll 1
    for (int kt = 0; kt <= qt; kt++) {
        ld_qk(fs + FK, K + (size_t)kt * 128 * DH);
        ld_v(fs + FV, Vt, kt);
        CP_COMMIT();
        CP_WAIT(0);
        __syncthreads();

        if (kt == 0) {                            // Q fragments are loop-invariant
            #pragma unroll
            for (int ks = 0; ks < 4; ks++)
                ldsm_x4(qf[ks], fsb + (FQ + lmRow * 72 + ks * 16 + gh * 8) * 2);
        }

        // ---- S = Q K^T : 16 rows x 128 cols per warp ----
        float s[16][4];
        #pragma unroll
        for (int nt = 0; nt < 16; nt++)
            #pragma unroll
            for (int r = 0; r < 4; r++) s[nt][r] = 0.f;

        #pragma unroll
        for (int ks = 0; ks < 4; ks++) {
            #pragma unroll
            for (int p = 0; p < 8; p++) {
                uint32_t bf[4];
                ldsm_x4(bf, fsb + (FK + (p * 16 + lrow) * 72 + ks * 16 + gh * 8) * 2);
                uint32_t b0[2] = { bf[0], bf[2] }, b1[2] = { bf[1], bf[3] };
                mma_f16(s[2*p],   qf[ks], b0);
                mma_f16(s[2*p+1], qf[ks], b1);
            }
        }

        // ---- causal mask (diagonal tile) ----
        if (kt == qt) {
            int r0 = rowA, r1 = rowA + 8;
            #pragma unroll
            for (int nt = 0; nt < 16; nt++) {
                #pragma unroll
                for (int e = 0; e < 2; e++) {
                    int col = nt * 8 + 2 * qc + e;
                    if (col > r0) s[nt][e]     = -1e30f;
                    if (col > r1) s[nt][2 + e] = -1e30f;
                }
            }
        }

        // ---- online softmax ----
        float tm0 = -1e30f, tm1 = -1e30f;
        #pragma unroll
        for (int nt = 0; nt < 16; nt++) {
            tm0 = fmaxf(tm0, fmaxf(s[nt][0], s[nt][1]));
            tm1 = fmaxf(tm1, fmaxf(s[nt][2], s[nt][3]));
        }
        tm0 = fmaxf(tm0, __shfl_xor_sync(0xffffffffu, tm0, 1));
        tm0 = fmaxf(tm0, __shfl_xor_sync(0xffffffffu, tm0, 2));
        tm1 = fmaxf(tm1, __shfl_xor_sync(0xffffffffu, tm1, 1));
        tm1 = fmaxf(tm1, __shfl_xor_sync(0xffffffffu, tm1, 2));

        float mn0 = fmaxf(m[0], tm0), mn1 = fmaxf(m[1], tm1);
        float c0 = __expf(m[0] - mn0), c1 = __expf(m[1] - mn1);
        m[0] = mn0; m[1] = mn1;

        float sum0 = 0.f, sum1 = 0.f;
        #pragma unroll
        for (int nt = 0; nt < 16; nt++) {
            float p0 = __expf(s[nt][0] - mn0);
            float p1 = __expf(s[nt][1] - mn0);
            float p2 = __expf(s[nt][2] - mn1);
            float p3 = __expf(s[nt][3] - mn1);
            sum0 += p0 + p1; sum1 += p2 + p3;
            *reinterpret_cast<__half2*>(&Ps[rowA * 136 + nt * 8 + 2 * qc]) =
                __floats2half2_rn(p0, p1);
            *reinterpret_cast<__half2*>(&Ps[(rowA + 8) * 136 + nt * 8 + 2 * qc]) =
                __floats2half2_rn(p2, p3);
        }
        sum0 += __shfl_xor_sync(0xffffffffu, sum0, 1);
        sum0 += __shfl_xor_sync(0xffffffffu, sum0, 2);
        sum1 += __shfl_xor_sync(0xffffffffu, sum1, 1);
        sum1 += __shfl_xor_sync(0xffffffffu, sum1, 2);
        l[0] = l[0] * c0 + sum0;
        l[1] = l[1] * c1 + sum1;

        #pragma unroll
        for (int nt = 0; nt < 8; nt++) {
            o[nt][0] *= c0; o[nt][1] *= c0;
            o[nt][2] *= c1; o[nt][3] *= c1;
        }
        __syncwarp();                          // P rows are warp-local

        // ---- O += P @ V ----
        #pragma unroll
        for (int ks = 0; ks < 8; ks++) {
            uint32_t pf[4];
            ldsm_x4(pf, fsb + (FP + lmRow * 136 + ks * 16 + gh * 8) * 2);
            #pragma unroll
            for (int p = 0; p < 4; p++) {
                uint32_t bf[4];
                ldsm_x4(bf, fsb + (FV + (p * 16 + lrow) * 136 + ks * 16 + gh * 8) * 2);
                uint32_t b0[2] = { bf[0], bf[2] }, b1[2] = { bf[1], bf[3] };
                mma_f16(o[2*p],   pf, b0);
                mma_f16(o[2*p+1], pf, b1);
            }
        }
        __syncthreads();                       // protect K/V before next cp.async
    }

    // ---- epilogue: O /= l, write fp16 [B,T,C] ----
    int b = bh >> 4, h = bh & 15;
    int t0 = qt * 128 + rowA;
    float inv0 = 1.f / l[0], inv1 = 1.f / l[1];
    #pragma unroll
    for (int nt = 0; nt < 8; nt++) {
        int col = h * 64 + nt * 8 + 2 * qc;
        *reinterpret_cast<__half2*>(&g_attnh[((size_t)(b * T_ + t0)) * C_ + col]) =
            __floats2half2_rn(o[nt][0] * inv0, o[nt][1] * inv0);
        *reinterpret_cast<__half2*>(&g_attnh[((size_t)(b * T_ + t0 + 8)) * C_ + col]) =
            __floats2half2_rn(o[nt][2] * inv1, o[nt][3] * inv1);
    }
}

// ================= LayerNorm (fp32 in -> fp16 out) =================
__global__ void __launch_bounds__(256) ln_kernel(const float* __restrict__ x,
                                                 const float* __restrict__ g,
                                                 const float* __restrict__ beta,
                                                 __half* __restrict__ out)
{
    int row = blockIdx.x, tid = threadIdx.x;
    float4 v = reinterpret_cast<const float4*>(x + (size_t)row * C_)[tid];
    float s  = v.x + v.y + v.z + v.w;
    float ss = v.x*v.x + v.y*v.y + v.z*v.z + v.w*v.w;
    __shared__ float shs[8], shss[8];
    #pragma unroll
    for (int o = 16; o; o >>= 1) {
        s  += __shfl_xor_sync(0xffffffffu, s,  o);
        ss += __shfl_xor_sync(0xffffffffu, ss, o);
    }
    if ((tid & 31) == 0) { shs[tid >> 5] = s; shss[tid >> 5] = ss; }
    __syncthreads();
    if (tid < 32) {
        float s2  = (tid < 8) ? shs[tid]  : 0.f;
        float ss2 = (tid < 8) ? shss[tid] : 0.f;
        #pragma unroll
        for (int o = 4; o; o >>= 1) {
            s2  += __shfl_xor_sync(0xffffffffu, s2,  o);
            ss2 += __shfl_xor_sync(0xffffffffu, ss2, o);
        }
        if (tid == 0) { shs[0] = s2; shss[0] = ss2; }
    }
    __syncthreads();
    float mean = shs[0] * (1.f / C_);
    float var  = shss[0] * (1.f / C_) - mean * mean;
    float inv  = rsqrtf(var + EPS_);
    float4 gg = reinterpret_cast<const float4*>(g)[tid];
    float4 bb = reinterpret_cast<const float4*>(beta)[tid];
    __half2 h0 = __floats2half2_rn(gg.x * (v.x - mean) * inv + bb.x,
                                   gg.y * (v.y - mean) * inv + bb.y);
    __half2 h1 = __floats2half2_rn(gg.z * (v.z - mean) * inv + bb.z,
                                   gg.w * (v.w - mean) * inv + bb.w);
    uint2 pk = { *(uint32_t*)&h0, *(uint32_t*)&h1 };
    reinterpret_cast<uint2*>(out + (size_t)row * C_)[tid] = pk;
}

// ================= launch =================
extern "C" void kernel_launch(void* const* d_in, const int* in_sizes, int n_in,
                              void* d_out, int out_size)
{
    const float* x     = (const float*)d_in[0];
    const float* Wq    = (const float*)d_in[1];
    const float* Wk    = (const float*)d_in[2];
    const float* Wv    = (const float*)d_in[3];
    const float* Wproj = (const float*)d_in[4];
    const float* bproj = (const float*)d_in[5];
    const float* W1    = (const float*)d_in[6];
    const float* b1    = (const float*)d_in[7];
    const float* W2    = (const float*)d_in[8];
    const float* b2    = (const float*)d_in[9];
    const float* g1    = (const float*)d_in[10];
    const float* beta1 = (const float*)d_in[11];
    const float* g2    = (const float*)d_in[12];
    const float* beta2 = (const float*)d_in[13];
    float* out = (float*)d_out;

    __half *xnh, *qkvh, *attnh, *h1h, *wqkvh, *wpth, *w1th, *w2th;
    float  *x1;
    cudaGetSymbolAddress((void**)&xnh,   g_xnh);
    cudaGetSymbolAddress((void**)&qkvh,  g_qkvh);
    cudaGetSymbolAddress((void**)&attnh, g_attnh);
    cudaGetSymbolAddress((void**)&h1h,   g_h1h);
    cudaGetSymbolAddress((void**)&x1,    g_x1);
    cudaGetSymbolAddress((void**)&wqkvh, g_wqkvh);
    cudaGetSymbolAddress((void**)&wpth,  g_wpth);
    cudaGetSymbolAddress((void**)&w1th,  g_w1th);
    cudaGetSymbolAddress((void**)&w2th,  g_w2th);

    cudaFuncSetAttribute(mma_gemm<EPI_QKV>,   cudaFuncAttributeMaxDynamicSharedMemorySize, SMEM_SZ);
    cudaFuncSetAttribute(mma_gemm<EPI_PROJ>,  cudaFuncAttributeMaxDynamicSharedMemorySize, SMEM_SZ);
    cudaFuncSetAttribute(mma_gemm<EPI_RELU>,  cudaFuncAttributeMaxDynamicSharedMemorySize, SMEM_SZ);
    cudaFuncSetAttribute(mma_gemm<EPI_RESID>, cudaFuncAttributeMaxDynamicSharedMemorySize, SMEM_SZ);
    cudaFuncSetAttribute(flash_kernel,        cudaFuncAttributeMaxDynamicSharedMemorySize, FA_SMEM);

    dim3 tp(32, 8);
    // order chosen so ncu (-s 5 -c 1) captures the QKV GEMM at launch index 5
    ln_kernel<<<M_, 256>>>(x, g1, beta1, xnh);                           // 0
    transpose_qkv_kernel<<<dim3(2, 32, 16), tp>>>(Wq, wqkvh);            // 1
    transpose_qkv_kernel<<<dim3(2, 32, 16), tp>>>(Wk, wqkvh + (size_t)C_ * C_);   // 2
    transpose_qkv_kernel<<<dim3(2, 32, 16), tp>>>(Wv, wqkvh + 2ll * C_ * C_);     // 3
    transpose_kernel<<<dim3(32, 32), tp>>>(Wproj, wpth);                 // 4
    mma_gemm<EPI_QKV><<<dim3(3 * C_ / BN, M_ / BM), 512, SMEM_SZ>>>(xnh, wqkvh, nullptr, nullptr, qkvh);  // 5
    flash_kernel<<<dim3(T_ / 128, B_ * H_), 256, FA_SMEM>>>();           // 6
    mma_gemm<EPI_PROJ><<<dim3(C_ / BN, M_ / BM), 512, SMEM_SZ>>>(attnh, wpth, bproj, x, x1);  // 7
    ln_kernel<<<M_, 256>>>(x1, g2, beta2, xnh);                          // 8
    transpose_kernel<<<dim3(32, 32), tp>>>(W1, w1th);                    // 9 (before mlp1)
    transpose_kernel<<<dim3(32, 32), tp>>>(W2, w2th);                    // 10
    mma_gemm<EPI_RELU><<<dim3(C_ / BN, M_ / BM), 512, SMEM_SZ>>>(xnh, w1th, b1, nullptr, h1h);   // 11
    mma_gemm<EPI_RESID><<<dim3(C_ / BN, M_ / BM), 512, SMEM_SZ>>>(h1h, w2th, b2, x1, out);       // 12
}

// round 8
// speedup vs baseline: 1.0810x; 1.0810x over previous
#include <cuda_runtime.h>
#include <cuda_fp16.h>
#include <math.h>
#include <cstdint>

#define B_   8
#define T_   1024
#define C_   1024
#define H_   16
#define DH   64
#define M_   (B_*T_)
#define KDIM 1024
#define EPS_ 1e-5f

// ---------------- scratch (device globals) ----------------
__device__ __half g_xnh  [M_*C_];
__device__ __half g_qkvh [3ll*M_*C_];      // q,k,v all [B,H,T,Dh] (q pre-scaled)
__device__ __half g_attnh[M_*C_];
__device__ __half g_h1h  [M_*C_];
__device__ float  g_x1   [M_*C_];
__device__ __half g_wqkvh[3ll*C_*C_];      // [N=3072][K=1024]
__device__ __half g_wpth [C_*C_];
__device__ __half g_w1th [C_*C_];
__device__ __half g_w2th [C_*C_];

// ================= helpers =================
__device__ __forceinline__ uint32_t smem_u32(const void* p) {
    uint32_t a;
    asm("{ .reg .u64 t; cvta.to.shared.u64 t, %1; cvt.u32.u64 %0, t; }" : "=r"(a) : "l"(p));
    return a;
}
__device__ __forceinline__ void cp_async16(uint32_t dst, const void* src) {
    asm volatile("cp.async.cg.shared.global [%0], [%1], 16;" :: "r"(dst), "l"(src));
}
#define CP_COMMIT() asm volatile("cp.async.commit_group;" ::: "memory")
#define CP_WAIT(n)  asm volatile("cp.async.wait_group %0;" :: "n"(n) : "memory")

__device__ __forceinline__ void mma_f16(float* d, const uint32_t* a, const uint32_t* b) {
    asm volatile(
        "mma.sync.aligned.m16n8k16.row.col.f32.f16.f16.f32 "
        "{%0,%1,%2,%3}, {%4,%5,%6,%7}, {%8,%9}, {%0,%1,%2,%3};"
        : "+f"(d[0]), "+f"(d[1]), "+f"(d[2]), "+f"(d[3])
        : "r"(a[0]), "r"(a[1]), "r"(a[2]), "r"(a[3]), "r"(b[0]), "r"(b[1]));
}
__device__ __forceinline__ void ldsm_x4(uint32_t* r, uint32_t addr) {
    asm volatile("ldmatrix.sync.aligned.m8n8.x4.shared.b16 {%0,%1,%2,%3}, [%4];"
        : "=r"(r[0]), "=r"(r[1]), "=r"(r[2]), "=r"(r[3]) : "r"(addr));
}
__device__ __forceinline__ void ldsm_x4_t(uint32_t* r, uint32_t addr) {
    asm volatile("ldmatrix.sync.aligned.m8n8.x4.trans.shared.b16 {%0,%1,%2,%3}, [%4];"
        : "=r"(r[0]), "=r"(r[1]), "=r"(r[2]), "=r"(r[3]) : "r"(addr));
}

// ================= weight transposes (fp32 -> fp16 [N][K]) ============
__global__ void __launch_bounds__(256) transpose_kernel(const float* __restrict__ in,
                                                        __half* __restrict__ out)
{
    __shared__ float tile[32][33];
    int tx = threadIdx.x, ty = threadIdx.y;
    int n0 = blockIdx.x * 32, k0 = blockIdx.y * 32;
    #pragma unroll
    for (int i = 0; i < 32; i += 8)
        tile[ty + i][tx] = in[(size_t)(k0 + ty + i) * C_ + n0 + tx];
    __syncthreads();
    #pragma unroll
    for (int i = 0; i < 32; i += 8)
        out[(size_t)(n0 + ty + i) * KDIM + k0 + tx] = __float2half_rn(tile[tx][ty + i]);
}

__global__ void __launch_bounds__(256) transpose_qkv_kernel(const float* __restrict__ in,
                                                            __half* __restrict__ out)
{
    __shared__ float tile[32][33];
    int tx = threadIdx.x, ty = threadIdx.y;
    int h = blockIdx.z;
    int d0 = blockIdx.x * 32, c0 = blockIdx.y * 32;
    #pragma unroll
    for (int i = 0; i < 32; i += 8)
        tile[ty + i][tx] = in[(size_t)h * (C_ * DH) + (size_t)(c0 + ty + i) * DH + d0 + tx];
    __syncthreads();
    #pragma unroll
    for (int i = 0; i < 32; i += 8)
        out[(size_t)(h * DH + d0 + ty + i) * KDIM + c0 + tx] = __float2half_rn(tile[tx][ty + i]);
}

// ================= fp16 GEMM: 128x128 tile, 256 thr, BK=64h, 3-stage, ldmatrix ====
enum { EPI_QKV = 0, EPI_PROJ = 1, EPI_RELU = 2, EPI_RESID = 3 };

#define BKH 64
#define NCHUNK (KDIM / BKH)                // 16
#define A_H (128*BKH)                      // 8192 halves
#define STG_H (2*A_H)                      // 16384 halves (32KB)
#define SMEM_SZ (3 * STG_H * 2)            // 96KB

__device__ __forceinline__ int hidx(int row, int grp, int off) {
    return row * 64 + ((grp ^ (row & 7)) << 3) + off;
}

template<int EPI>
__global__ void __launch_bounds__(256) mma_gemm(
    const __half* __restrict__ A,      // [M][1024]
    const __half* __restrict__ Bt,     // [Ntot][1024]
    const float*  __restrict__ bias,
    const float*  __restrict__ resid,
    void*         __restrict__ outv)
{
    extern __shared__ __half sm[];
    int tid = threadIdx.x, wid = tid >> 5, lane = tid & 31;
    int warpM = wid & 3, warpN = wid >> 2;      // 4 x 2 warps
    int qrow = lane >> 2, qc = lane & 3;
    int lrow = lane & 15, gh = lane >> 4;
    int mBase = blockIdx.y * 128, nBase = blockIdx.x * 128;

    const __half* aSrc = A  + (size_t)mBase * KDIM;
    const __half* bSrc = Bt + (size_t)nBase * KDIM;

    auto load_stage = [&](int c, int s) {
        __half* dA = sm + s * STG_H;
        __half* dB = dA + A_H;
        #pragma unroll
        for (int i = 0; i < 4; i++) {
            int id = tid + i * 256, r = id >> 3, g = id & 7;
            cp_async16(smem_u32(dA + hidx(r, g, 0)),
                       aSrc + (size_t)r * KDIM + c * BKH + g * 8);
            cp_async16(smem_u32(dB + hidx(r, g, 0)),
                       bSrc + (size_t)r * KDIM + c * BKH + g * 8);
        }
    };

    int rA[2], rB[4];
    rA[0] = warpM * 32 + lrow;  rA[1] = rA[0] + 16;
    #pragma unroll
    for (int p = 0; p < 4; p++) rB[p] = warpN * 64 + p * 16 + lrow;

    float acc[2][8][4];
    #pragma unroll
    for (int mt = 0; mt < 2; mt++)
        #pragma unroll
        for (int nt = 0; nt < 8; nt++)
            #pragma unroll
            for (int r = 0; r < 4; r++) acc[mt][nt][r] = 0.f;

    load_stage(0, 0); CP_COMMIT();
    load_stage(1, 1); CP_COMMIT();

    uint32_t smBase = smem_u32(sm);

    #pragma unroll 1
    for (int c = 0; c < NCHUNK; c++) {
        if (c < NCHUNK - 2) { CP_WAIT(1); } else { CP_WAIT(0); }
        __syncthreads();
        if (c + 2 < NCHUNK) { load_stage(c + 2, (c + 2) % 3); CP_COMMIT(); }

        uint32_t baseA = smBase + (c % 3) * (STG_H * 2);
        uint32_t baseB = baseA + A_H * 2;

        #pragma unroll
        for (int ks = 0; ks < 4; ks++) {
            int grp = 2 * ks + gh;
            uint32_t af[2][4];
            ldsm_x4(af[0], baseA + (rA[0] * 64 + ((grp ^ (rA[0] & 7)) << 3)) * 2);
            ldsm_x4(af[1], baseA + (rA[1] * 64 + ((grp ^ (rA[1] & 7)) << 3)) * 2);
            #pragma unroll
            for (int p = 0; p < 4; p++) {
                uint32_t bf[4];
                ldsm_x4(bf, baseB + (rB[p] * 64 + ((grp ^ (rB[p] & 7)) << 3)) * 2);
                uint32_t b0[2] = { bf[0], bf[2] }, b1[2] = { bf[1], bf[3] };
                mma_f16(acc[0][2*p],   af[0], b0);
                mma_f16(acc[1][2*p],   af[1], b0);
                mma_f16(acc[0][2*p+1], af[0], b1);
                mma_f16(acc[1][2*p+1], af[1], b1);
            }
        }
    }

    // ---- epilogue ----
    #pragma unroll
    for (int mt = 0; mt < 2; mt++) {
        #pragma unroll
        for (int r = 0; r < 2; r++) {
            int m = mBase + warpM * 32 + mt * 16 + qrow + r * 8;
            #pragma unroll
            for (int nt = 0; nt < 8; nt++) {
                int col = nBase + warpN * 64 + nt * 8 + qc * 2;
                float vx = acc[mt][nt][r * 2], vy = acc[mt][nt][r * 2 + 1];
                if (EPI == EPI_QKV) {
                    __half* out = (__half*)outv;
                    int which = col >> 10, nn = col & 1023;
                    int h = nn >> 6, d = nn & 63;
                    int b = m >> 10, t = m & 1023;
                    float sc = (which == 0) ? 0.125f : 1.f;   // q pre-scaled by Dh^-0.5
                    *reinterpret_cast<__half2*>(
                        &out[(size_t)which * (M_ * C_) +
                             (((size_t)(b * H_ + h) * T_ + t) * DH + d)]) =
                        __floats2half2_rn(vx * sc, vy * sc);
                } else if (EPI == EPI_RELU) {
                    __half* out = (__half*)outv;
                    size_t idx = (size_t)m * C_ + col;
                    float ox = fmaxf(vx + bias[col], 0.f);
                    float oy = fmaxf(vy + bias[col + 1], 0.f);
                    *reinterpret_cast<__half2*>(&out[idx]) = __floats2half2_rn(ox, oy);
                } else {
                    float* out = (float*)outv;
                    size_t idx = (size_t)m * C_ + col;
                    float2 rs = *reinterpret_cast<const float2*>(&resid[idx]);
                    float2 o = { vx + bias[col] + rs.x, vy + bias[col + 1] + rs.y };
                    *reinterpret_cast<float2*>(&out[idx]) = o;
                }
            }
        }
    }
}

// ================= fused flash attention: register-P, trans-V, 2-stage K/V =======
#define FQ  0
#define FK0 9216
#define FK1 18432
#define FV0 27648
#define FV1 36864
#define FA_SMEM (46080 * 2)                // 92160 bytes

__global__ void __launch_bounds__(256) flash_kernel()
{
    extern __shared__ __half fs[];
    int tid = threadIdx.x, wid = tid >> 5, lane = tid & 31;
    int qrow = lane >> 2, qc = lane & 3;
    int lrow = lane & 15, gh = lane >> 4;
    int kr  = (lane & 7) | ((lane & 16) >> 1);   // trans-ldsm key row
    int dof = lane & 8;                          // trans-ldsm dim offset
    int qt = gridDim.x - 1 - blockIdx.x;
    int bh = blockIdx.y;

    const __half* Q = g_qkvh + ((size_t)bh * T_ + qt * 128) * DH;
    const __half* K = g_qkvh + (size_t)M_ * C_  + (size_t)bh * T_ * DH;
    const __half* V = g_qkvh + 2ll * M_ * C_    + (size_t)bh * T_ * DH;

    // 128 rows x 64 halves, stride 72 (conflict-free for ldmatrix)
    auto ldtile = [&](int dst, const __half* src) {
        #pragma unroll
        for (int i = 0; i < 4; i++) {
            int id = tid + i * 256;
            int row = id >> 3, j = id & 7;
            cp_async16(smem_u32(fs + dst + row * 72 + j * 8), src + row * 64 + j * 8);
        }
    };

    // group 0: Q + K0 + V0
    ldtile(FQ, Q);
    ldtile(FK0, K);
    ldtile(FV0, V);
    CP_COMMIT();

    int rowA = wid * 16 + qrow;
    int lmRow = wid * 16 + lrow;
    uint32_t fsb = smem_u32(fs);

    float m[2] = { -1e30f, -1e30f }, l[2] = { 0.f, 0.f };
    float o[8][4];
    #pragma unroll
    for (int nt = 0; nt < 8; nt++)
        #pragma unroll
        for (int r = 0; r < 4; r++) o[nt][r] = 0.f;

    uint32_t qf[4][4];

    #pragma unroll 1
    for (int kt = 0; kt <= qt; kt++) {
        __syncthreads();                       // all warps done with buf (kt+1)&1
        if (kt + 1 <= qt) {
            ldtile((kt & 1) ? FK0 : FK1, K + (size_t)(kt + 1) * 128 * DH);
            ldtile((kt & 1) ? FV0 : FV1, V + (size_t)(kt + 1) * 128 * DH);
            CP_COMMIT();
            CP_WAIT(1);                        // group kt arrived
        } else {
            CP_WAIT(0);
        }
        __syncthreads();                       // visibility of group kt

        int FKb = (kt & 1) ? FK1 : FK0;
        int FVb = (kt & 1) ? FV1 : FV0;

        if (kt == 0) {                         // Q fragments are loop-invariant
            #pragma unroll
            for (int ks = 0; ks < 4; ks++)
                ldsm_x4(qf[ks], fsb + (FQ + lmRow * 72 + ks * 16 + gh * 8) * 2);
        }

        // ---- S = Q K^T : 16 rows x 128 cols per warp ----
        float s[16][4];
        #pragma unroll
        for (int nt = 0; nt < 16; nt++)
            #pragma unroll
            for (int r = 0; r < 4; r++) s[nt][r] = 0.f;

        #pragma unroll
        for (int ks = 0; ks < 4; ks++) {
            #pragma unroll
            for (int p = 0; p < 8; p++) {
                uint32_t bf[4];
                ldsm_x4(bf, fsb + (FKb + (p * 16 + lrow) * 72 + ks * 16 + gh * 8) * 2);
                uint32_t b0[2] = { bf[0], bf[2] }, b1[2] = { bf[1], bf[3] };
                mma_f16(s[2*p],   qf[ks], b0);
                mma_f16(s[2*p+1], qf[ks], b1);
            }
        }

        // ---- causal mask (diagonal tile) ----
        if (kt == qt) {
            int r0 = rowA, r1 = rowA + 8;
            #pragma unroll
            for (int nt = 0; nt < 16; nt++) {
                #pragma unroll
                for (int e = 0; e < 2; e++) {
                    int col = nt * 8 + 2 * qc + e;
                    if (col > r0) s[nt][e]     = -1e30f;
                    if (col > r1) s[nt][2 + e] = -1e30f;
                }
            }
        }

        // ---- online softmax (P stays in registers, FA2 layout) ----
        float tm0 = -1e30f, tm1 = -1e30f;
        #pragma unroll
        for (int nt = 0; nt < 16; nt++) {
            tm0 = fmaxf(tm0, fmaxf(s[nt][0], s[nt][1]));
            tm1 = fmaxf(tm1, fmaxf(s[nt][2], s[nt][3]));
        }
        tm0 = fmaxf(tm0, __shfl_xor_sync(0xffffffffu, tm0, 1));
        tm0 = fmaxf(tm0, __shfl_xor_sync(0xffffffffu, tm0, 2));
        tm1 = fmaxf(tm1, __shfl_xor_sync(0xffffffffu, tm1, 1));
        tm1 = fmaxf(tm1, __shfl_xor_sync(0xffffffffu, tm1, 2));

        float mn0 = fmaxf(m[0], tm0), mn1 = fmaxf(m[1], tm1);
        float c0 = __expf(m[0] - mn0), c1 = __expf(m[1] - mn1);
        m[0] = mn0; m[1] = mn1;

        float sum0 = 0.f, sum1 = 0.f;
        uint32_t pfr[16][2];
        #pragma unroll
        for (int nt = 0; nt < 16; nt++) {
            float p0 = __expf(s[nt][0] - mn0);
            float p1 = __expf(s[nt][1] - mn0);
            float p2 = __expf(s[nt][2] - mn1);
            float p3 = __expf(s[nt][3] - mn1);
            sum0 += p0 + p1; sum1 += p2 + p3;
            __half2 h01 = __floats2half2_rn(p0, p1);
            __half2 h23 = __floats2half2_rn(p2, p3);
            pfr[nt][0] = *reinterpret_cast<uint32_t*>(&h01);
            pfr[nt][1] = *reinterpret_cast<uint32_t*>(&h23);
        }
        sum0 += __shfl_xor_sync(0xffffffffu, sum0, 1);
        sum0 += __shfl_xor_sync(0xffffffffu, sum0, 2);
        sum1 += __shfl_xor_sync(0xffffffffu, sum1, 1);
        sum1 += __shfl_xor_sync(0xffffffffu, sum1, 2);
        l[0] = l[0] * c0 + sum0;
        l[1] = l[1] * c1 + sum1;

        #pragma unroll
        for (int nt = 0; nt < 8; nt++) {
            o[nt][0] *= c0; o[nt][1] *= c0;
            o[nt][2] *= c1; o[nt][3] *= c1;
        }

        // ---- O += P @ V : P from registers, V via ldmatrix.trans ----
        #pragma unroll
        for (int ks = 0; ks < 8; ks++) {
            uint32_t af[4] = { pfr[2*ks][0], pfr[2*ks][1],
                               pfr[2*ks+1][0], pfr[2*ks+1][1] };
            #pragma unroll
            for (int p = 0; p < 4; p++) {
                uint32_t bf[4];
                ldsm_x4_t(bf, fsb + (FVb + (ks * 16 + kr) * 72 + p * 16 + dof) * 2);
                uint32_t b0[2] = { bf[0], bf[2] }, b1[2] = { bf[1], bf[3] };
                mma_f16(o[2*p],   af, b0);
                mma_f16(o[2*p+1], af, b1);
            }
        }
    }

    // ---- epilogue: O /= l, write fp16 [B,T,C] ----
    int b = bh >> 4, h = bh & 15;
    int t0 = qt * 128 + rowA;
    float inv0 = 1.f / l[0], inv1 = 1.f / l[1];
    #pragma unroll
    for (int nt = 0; nt < 8; nt++) {
        int col = h * 64 + nt * 8 + 2 * qc;
        *reinterpret_cast<__half2*>(&g_attnh[((size_t)(b * T_ + t0)) * C_ + col]) =
            __floats2half2_rn(o[nt][0] * inv0, o[nt][1] * inv0);
        *reinterpret_cast<__half2*>(&g_attnh[((size_t)(b * T_ + t0 + 8)) * C_ + col]) =
            __floats2half2_rn(o[nt][2] * inv1, o[nt][3] * inv1);
    }
}

// ================= LayerNorm (fp32 in -> fp16 out) =================
__global__ void __launch_bounds__(256) ln_kernel(const float* __restrict__ x,
                                                 const float* __restrict__ g,
                                                 const float* __restrict__ beta,
                                                 __half* __restrict__ out)
{
    int row = blockIdx.x, tid = threadIdx.x;
    float4 v = reinterpret_cast<const float4*>(x + (size_t)row * C_)[tid];
    float s  = v.x + v.y + v.z + v.w;
    float ss = v.x*v.x + v.y*v.y + v.z*v.z + v.w*v.w;
    __shared__ float shs[8], shss[8];
    #pragma unroll
    for (int o = 16; o; o >>= 1) {
        s  += __shfl_xor_sync(0xffffffffu, s,  o);
        ss += __shfl_xor_sync(0xffffffffu, ss, o);
    }
    if ((tid & 31) == 0) { shs[tid >> 5] = s; shss[tid >> 5] = ss; }
    __syncthreads();
    if (tid < 32) {
        float s2  = (tid < 8) ? shs[tid]  : 0.f;
        float ss2 = (tid < 8) ? shss[tid] : 0.f;
        #pragma unroll
        for (int o = 4; o; o >>= 1) {
            s2  += __shfl_xor_sync(0xffffffffu, s2,  o);
            ss2 += __shfl_xor_sync(0xffffffffu, ss2, o);
        }
        if (tid == 0) { shs[0] = s2; shss[0] = ss2; }
    }
    __syncthreads();
    float mean = shs[0] * (1.f / C_);
    float var  = shss[0] * (1.f / C_) - mean * mean;
    float inv  = rsqrtf(var + EPS_);
    float4 gg = reinterpret_cast<const float4*>(g)[tid];
    float4 bb = reinterpret_cast<const float4*>(beta)[tid];
    __half2 h0 = __floats2half2_rn(gg.x * (v.x - mean) * inv + bb.x,
                                   gg.y * (v.y - mean) * inv + bb.y);
    __half2 h1 = __floats2half2_rn(gg.z * (v.z - mean) * inv + bb.z,
                                   gg.w * (v.w - mean) * inv + bb.w);
    uint2 pk = { *(uint32_t*)&h0, *(uint32_t*)&h1 };
    reinterpret_cast<uint2*>(out + (size_t)row * C_)[tid] = pk;
}

// ================= launch =================
extern "C" void kernel_launch(void* const* d_in, const int* in_sizes, int n_in,
                              void* d_out, int out_size)
{
    const float* x     = (const float*)d_in[0];
    const float* Wq    = (const float*)d_in[1];
    const float* Wk    = (const float*)d_in[2];
    const float* Wv    = (const float*)d_in[3];
    const float* Wproj = (const float*)d_in[4];
    const float* bproj = (const float*)d_in[5];
    const float* W1    = (const float*)d_in[6];
    const float* b1    = (const float*)d_in[7];
    const float* W2    = (const float*)d_in[8];
    const float* b2    = (const float*)d_in[9];
    const float* g1    = (const float*)d_in[10];
    const float* beta1 = (const float*)d_in[11];
    const float* g2    = (const float*)d_in[12];
    const float* beta2 = (const float*)d_in[13];
    float* out = (float*)d_out;

    __half *xnh, *qkvh, *attnh, *h1h, *wqkvh, *wpth, *w1th, *w2th;
    float  *x1;
    cudaGetSymbolAddress((void**)&xnh,   g_xnh);
    cudaGetSymbolAddress((void**)&qkvh,  g_qkvh);
    cudaGetSymbolAddress((void**)&attnh, g_attnh);
    cudaGetSymbolAddress((void**)&h1h,   g_h1h);
    cudaGetSymbolAddress((void**)&x1,    g_x1);
    cudaGetSymbolAddress((void**)&wqkvh, g_wqkvh);
    cudaGetSymbolAddress((void**)&wpth,  g_wpth);
    cudaGetSymbolAddress((void**)&w1th,  g_w1th);
    cudaGetSymbolAddress((void**)&w2th,  g_w2th);

    cudaFuncSetAttribute(mma_gemm<EPI_QKV>,   cudaFuncAttributeMaxDynamicSharedMemorySize, SMEM_SZ);
    cudaFuncSetAttribute(mma_gemm<EPI_PROJ>,  cudaFuncAttributeMaxDynamicSharedMemorySize, SMEM_SZ);
    cudaFuncSetAttribute(mma_gemm<EPI_RELU>,  cudaFuncAttributeMaxDynamicSharedMemorySize, SMEM_SZ);
    cudaFuncSetAttribute(mma_gemm<EPI_RESID>, cudaFuncAttributeMaxDynamicSharedMemorySize, SMEM_SZ);
    cudaFuncSetAttribute(flash_kernel,        cudaFuncAttributeMaxDynamicSharedMemorySize, FA_SMEM);

    dim3 tp(32, 8);
    // order chosen so ncu (-s 5 -c 1) captures the QKV GEMM at launch index 5
    ln_kernel<<<M_, 256>>>(x, g1, beta1, xnh);                                    // 0
    transpose_qkv_kernel<<<dim3(2, 32, 16), tp>>>(Wq, wqkvh);                     // 1
    transpose_qkv_kernel<<<dim3(2, 32, 16), tp>>>(Wk, wqkvh + (size_t)C_ * C_);   // 2
    transpose_qkv_kernel<<<dim3(2, 32, 16), tp>>>(Wv, wqkvh + 2ll * C_ * C_);     // 3
    transpose_kernel<<<dim3(32, 32), tp>>>(Wproj, wpth);                          // 4
    mma_gemm<EPI_QKV><<<dim3(3 * C_ / 128, M_ / 128), 256, SMEM_SZ>>>(xnh, wqkvh, nullptr, nullptr, qkvh);  // 5
    flash_kernel<<<dim3(T_ / 128, B_ * H_), 256, FA_SMEM>>>();                    // 6
    mma_gemm<EPI_PROJ><<<dim3(C_ / 128, M_ / 128), 256, SMEM_SZ>>>(attnh, wpth, bproj, x, x1);  // 7
    ln_kernel<<<M_, 256>>>(x1, g2, beta2, xnh);                                   // 8
    transpose_kernel<<<dim3(32, 32), tp>>>(W1, w1th);                             // 9
    transpose_kernel<<<dim3(32, 32), tp>>>(W2, w2th);                             // 10
    mma_gemm<EPI_RELU><<<dim3(C_ / 128, M_ / 128), 256, SMEM_SZ>>>(xnh, w1th, b1, nullptr, h1h);   // 11
    mma_gemm<EPI_RESID><<<dim3(C_ / 128, M_ / 128), 256, SMEM_SZ>>>(h1h, w2th, b2, x1, out);       // 12
}

// round 9
// speedup vs baseline: 1.0916x; 1.0098x over previous
#include <cuda_runtime.h>
#include <cuda_fp16.h>
#include <math.h>
#include <cstdint>

#define B_   8
#define T_   1024
#define C_   1024
#define H_   16
#define DH   64
#define M_   (B_*T_)
#define KDIM 1024
#define EPS_ 1e-5f

// ---------------- scratch (device globals) ----------------
__device__ __half g_xnh  [M_*C_];
__device__ __half g_qkvh [3ll*M_*C_];      // q,k,v all [B,H,T,Dh] (q pre-scaled)
__device__ __half g_attnh[M_*C_];
__device__ __half g_h1h  [M_*C_];
__device__ float  g_x1   [M_*C_];
__device__ __half g_wqkvh[3ll*C_*C_];      // [N=3072][K=1024]
__device__ __half g_wpth [C_*C_];
__device__ __half g_w1th [C_*C_];
__device__ __half g_w2th [C_*C_];

// ================= helpers =================
__device__ __forceinline__ uint32_t smem_u32(const void* p) {
    uint32_t a;
    asm("{ .reg .u64 t; cvta.to.shared.u64 t, %1; cvt.u32.u64 %0, t; }" : "=r"(a) : "l"(p));
    return a;
}
__device__ __forceinline__ void cp_async16(uint32_t dst, const void* src) {
    asm volatile("cp.async.cg.shared.global [%0], [%1], 16;" :: "r"(dst), "l"(src));
}
#define CP_COMMIT() asm volatile("cp.async.commit_group;" ::: "memory")
#define CP_WAIT(n)  asm volatile("cp.async.wait_group %0;" :: "n"(n) : "memory")

__device__ __forceinline__ void mma_f16(float* d, const uint32_t* a, const uint32_t* b) {
    asm volatile(
        "mma.sync.aligned.m16n8k16.row.col.f32.f16.f16.f32 "
        "{%0,%1,%2,%3}, {%4,%5,%6,%7}, {%8,%9}, {%0,%1,%2,%3};"
        : "+f"(d[0]), "+f"(d[1]), "+f"(d[2]), "+f"(d[3])
        : "r"(a[0]), "r"(a[1]), "r"(a[2]), "r"(a[3]), "r"(b[0]), "r"(b[1]));
}
// f16 accumulate variant (2x rate; used only for flash S with K=64 reduction)
__device__ __forceinline__ void mma_f16acc(uint32_t* d, const uint32_t* a, const uint32_t* b) {
    asm volatile(
        "mma.sync.aligned.m16n8k16.row.col.f16.f16.f16.f16 "
        "{%0,%1}, {%2,%3,%4,%5}, {%6,%7}, {%0,%1};"
        : "+r"(d[0]), "+r"(d[1])
        : "r"(a[0]), "r"(a[1]), "r"(a[2]), "r"(a[3]), "r"(b[0]), "r"(b[1]));
}
__device__ __forceinline__ void ldsm_x4(uint32_t* r, uint32_t addr) {
    asm volatile("ldmatrix.sync.aligned.m8n8.x4.shared.b16 {%0,%1,%2,%3}, [%4];"
        : "=r"(r[0]), "=r"(r[1]), "=r"(r[2]), "=r"(r[3]) : "r"(addr));
}
__device__ __forceinline__ void ldsm_x4_t(uint32_t* r, uint32_t addr) {
    asm volatile("ldmatrix.sync.aligned.m8n8.x4.trans.shared.b16 {%0,%1,%2,%3}, [%4];"
        : "=r"(r[0]), "=r"(r[1]), "=r"(r[2]), "=r"(r[3]) : "r"(addr));
}

// ================= fused weight conversion (6 matrices, ONE launch) ============
// grid (32, 32, 6); z 0..2: plain [K,N]->[N,K] for Wproj/W1/W2; z 3..5: [H,C,Dh]->[h*64+d][c]
__global__ void __launch_bounds__(256) convert_weights_kernel(
    const float* __restrict__ Wp, const float* __restrict__ W1, const float* __restrict__ W2,
    const float* __restrict__ Wq, const float* __restrict__ Wk, const float* __restrict__ Wv)
{
    __shared__ float tile[32][33];
    int tx = threadIdx.x, ty = threadIdx.y;
    int z = blockIdx.z;
    if (z < 3) {
        const float* in = (z == 0) ? Wp : (z == 1) ? W1 : W2;
        __half* out = (z == 0) ? g_wpth : (z == 1) ? g_w1th : g_w2th;
        int n0 = blockIdx.x * 32, k0 = blockIdx.y * 32;
        #pragma unroll
        for (int i = 0; i < 32; i += 8)
            tile[ty + i][tx] = in[(size_t)(k0 + ty + i) * C_ + n0 + tx];
        __syncthreads();
        #pragma unroll
        for (int i = 0; i < 32; i += 8)
            out[(size_t)(n0 + ty + i) * KDIM + k0 + tx] = __float2half_rn(tile[tx][ty + i]);
    } else {
        const float* in = (z == 3) ? Wq : (z == 4) ? Wk : Wv;
        __half* out = g_wqkvh + (size_t)(z - 3) * C_ * C_;
        int h = blockIdx.x >> 1, d0 = (blockIdx.x & 1) * 32, c0 = blockIdx.y * 32;
        #pragma unroll
        for (int i = 0; i < 32; i += 8)
            tile[ty + i][tx] = in[(size_t)h * (C_ * DH) + (size_t)(c0 + ty + i) * DH + d0 + tx];
        __syncthreads();
        #pragma unroll
        for (int i = 0; i < 32; i += 8)
            out[(size_t)(h * DH + d0 + ty + i) * KDIM + c0 + tx] = __float2half_rn(tile[tx][ty + i]);
    }
}

// ================= fp16 GEMM: 128x128 tile, 256 thr, BK=64h, 3-stage, ldmatrix ====
enum { EPI_QKV = 0, EPI_PROJ = 1, EPI_RELU = 2, EPI_RESID = 3 };

#define BKH 64
#define NCHUNK (KDIM / BKH)                // 16
#define A_H (128*BKH)                      // 8192 halves
#define STG_H (2*A_H)                      // 16384 halves (32KB)
#define SMEM_SZ (3 * STG_H * 2)            // 96KB

__device__ __forceinline__ int hidx(int row, int grp, int off) {
    return row * 64 + ((grp ^ (row & 7)) << 3) + off;
}

template<int EPI>
__global__ void __launch_bounds__(256) mma_gemm(
    const __half* __restrict__ A,      // [M][1024]
    const __half* __restrict__ Bt,     // [Ntot][1024]
    const float*  __restrict__ bias,
    const float*  __restrict__ resid,
    void*         __restrict__ outv)
{
    extern __shared__ __half sm[];
    int tid = threadIdx.x, wid = tid >> 5, lane = tid & 31;
    int warpM = wid & 3, warpN = wid >> 2;      // 4 x 2 warps
    int qrow = lane >> 2, qc = lane & 3;
    int lrow = lane & 15, gh = lane >> 4;
    int mBase = blockIdx.y * 128, nBase = blockIdx.x * 128;

    const __half* aSrc = A  + (size_t)mBase * KDIM;
    const __half* bSrc = Bt + (size_t)nBase * KDIM;

    auto load_stage = [&](int c, int s) {
        __half* dA = sm + s * STG_H;
        __half* dB = dA + A_H;
        #pragma unroll
        for (int i = 0; i < 4; i++) {
            int id = tid + i * 256, r = id >> 3, g = id & 7;
            cp_async16(smem_u32(dA + hidx(r, g, 0)),
                       aSrc + (size_t)r * KDIM + c * BKH + g * 8);
            cp_async16(smem_u32(dB + hidx(r, g, 0)),
                       bSrc + (size_t)r * KDIM + c * BKH + g * 8);
        }
    };

    int rA[2], rB[4];
    rA[0] = warpM * 32 + lrow;  rA[1] = rA[0] + 16;
    #pragma unroll
    for (int p = 0; p < 4; p++) rB[p] = warpN * 64 + p * 16 + lrow;

    float acc[2][8][4];
    #pragma unroll
    for (int mt = 0; mt < 2; mt++)
        #pragma unroll
        for (int nt = 0; nt < 8; nt++)
            #pragma unroll
            for (int r = 0; r < 4; r++) acc[mt][nt][r] = 0.f;

    load_stage(0, 0); CP_COMMIT();
    load_stage(1, 1); CP_COMMIT();

    uint32_t smBase = smem_u32(sm);

    #pragma unroll 1
    for (int c = 0; c < NCHUNK; c++) {
        if (c < NCHUNK - 2) { CP_WAIT(1); } else { CP_WAIT(0); }
        __syncthreads();
        if (c + 2 < NCHUNK) { load_stage(c + 2, (c + 2) % 3); CP_COMMIT(); }

        uint32_t baseA = smBase + (c % 3) * (STG_H * 2);
        uint32_t baseB = baseA + A_H * 2;

        #pragma unroll
        for (int ks = 0; ks < 4; ks++) {
            int grp = 2 * ks + gh;
            uint32_t af[2][4];
            ldsm_x4(af[0], baseA + (rA[0] * 64 + ((grp ^ (rA[0] & 7)) << 3)) * 2);
            ldsm_x4(af[1], baseA + (rA[1] * 64 + ((grp ^ (rA[1] & 7)) << 3)) * 2);
            #pragma unroll
            for (int p = 0; p < 4; p++) {
                uint32_t bf[4];
                ldsm_x4(bf, baseB + (rB[p] * 64 + ((grp ^ (rB[p] & 7)) << 3)) * 2);
                uint32_t b0[2] = { bf[0], bf[2] }, b1[2] = { bf[1], bf[3] };
                mma_f16(acc[0][2*p],   af[0], b0);
                mma_f16(acc[1][2*p],   af[1], b0);
                mma_f16(acc[0][2*p+1], af[0], b1);
                mma_f16(acc[1][2*p+1], af[1], b1);
            }
        }
    }

    // ---- epilogue ----
    #pragma unroll
    for (int mt = 0; mt < 2; mt++) {
        #pragma unroll
        for (int r = 0; r < 2; r++) {
            int m = mBase + warpM * 32 + mt * 16 + qrow + r * 8;
            #pragma unroll
            for (int nt = 0; nt < 8; nt++) {
                int col = nBase + warpN * 64 + nt * 8 + qc * 2;
                float vx = acc[mt][nt][r * 2], vy = acc[mt][nt][r * 2 + 1];
                if (EPI == EPI_QKV) {
                    __half* out = (__half*)outv;
                    int which = col >> 10, nn = col & 1023;
                    int h = nn >> 6, d = nn & 63;
                    int b = m >> 10, t = m & 1023;
                    float sc = (which == 0) ? 0.125f : 1.f;   // q pre-scaled by Dh^-0.5
                    *reinterpret_cast<__half2*>(
                        &out[(size_t)which * (M_ * C_) +
                             (((size_t)(b * H_ + h) * T_ + t) * DH + d)]) =
                        __floats2half2_rn(vx * sc, vy * sc);
                } else if (EPI == EPI_RELU) {
                    __half* out = (__half*)outv;
                    size_t idx = (size_t)m * C_ + col;
                    float ox = fmaxf(vx + bias[col], 0.f);
                    float oy = fmaxf(vy + bias[col + 1], 0.f);
                    *reinterpret_cast<__half2*>(&out[idx]) = __floats2half2_rn(ox, oy);
                } else {
                    float* out = (float*)outv;
                    size_t idx = (size_t)m * C_ + col;
                    float2 rs = *reinterpret_cast<const float2*>(&resid[idx]);
                    float2 o = { vx + bias[col] + rs.x, vy + bias[col + 1] + rs.y };
                    *reinterpret_cast<float2*>(&out[idx]) = o;
                }
            }
        }
    }
}

// ================= fused flash attention: register-P, f16-acc S, 2-stage K/V =====
#define FQ  0
#define FK0 9216
#define FK1 18432
#define FV0 27648
#define FV1 36864
#define FA_SMEM (46080 * 2)                // 92160 bytes

__global__ void __launch_bounds__(256) flash_kernel()
{
    extern __shared__ __half fs[];
    int tid = threadIdx.x, wid = tid >> 5, lane = tid & 31;
    int qrow = lane >> 2, qc = lane & 3;
    int lrow = lane & 15, gh = lane >> 4;
    int kr  = (lane & 7) | ((lane & 16) >> 1);   // trans-ldsm key row
    int dof = lane & 8;                          // trans-ldsm dim offset
    int qt = gridDim.x - 1 - blockIdx.x;
    int bh = blockIdx.y;

    const __half* Q = g_qkvh + ((size_t)bh * T_ + qt * 128) * DH;
    const __half* K = g_qkvh + (size_t)M_ * C_  + (size_t)bh * T_ * DH;
    const __half* V = g_qkvh + 2ll * M_ * C_    + (size_t)bh * T_ * DH;

    auto ldtile = [&](int dst, const __half* src) {
        #pragma unroll
        for (int i = 0; i < 4; i++) {
            int id = tid + i * 256;
            int row = id >> 3, j = id & 7;
            cp_async16(smem_u32(fs + dst + row * 72 + j * 8), src + row * 64 + j * 8);
        }
    };

    ldtile(FQ, Q);
    ldtile(FK0, K);
    ldtile(FV0, V);
    CP_COMMIT();

    int rowA = wid * 16 + qrow;
    int lmRow = wid * 16 + lrow;
    uint32_t fsb = smem_u32(fs);

    float m[2] = { -1e30f, -1e30f }, l[2] = { 0.f, 0.f };
    float o[8][4];
    #pragma unroll
    for (int nt = 0; nt < 8; nt++)
        #pragma unroll
        for (int r = 0; r < 4; r++) o[nt][r] = 0.f;

    uint32_t qf[4][4];

    #pragma unroll 1
    for (int kt = 0; kt <= qt; kt++) {
        __syncthreads();
        if (kt + 1 <= qt) {
            ldtile((kt & 1) ? FK0 : FK1, K + (size_t)(kt + 1) * 128 * DH);
            ldtile((kt & 1) ? FV0 : FV1, V + (size_t)(kt + 1) * 128 * DH);
            CP_COMMIT();
            CP_WAIT(1);
        } else {
            CP_WAIT(0);
        }
        __syncthreads();

        int FKb = (kt & 1) ? FK1 : FK0;
        int FVb = (kt & 1) ? FV1 : FV0;

        if (kt == 0) {
            #pragma unroll
            for (int ks = 0; ks < 4; ks++)
                ldsm_x4(qf[ks], fsb + (FQ + lmRow * 72 + ks * 16 + gh * 8) * 2);
        }

        // ---- S = Q K^T, fp16 accumulate (K=64 reduction; 2x HMMA rate) ----
        uint32_t sh[16][2];
        #pragma unroll
        for (int nt = 0; nt < 16; nt++) { sh[nt][0] = 0u; sh[nt][1] = 0u; }

        #pragma unroll
        for (int ks = 0; ks < 4; ks++) {
            #pragma unroll
            for (int p = 0; p < 8; p++) {
                uint32_t bf[4];
                ldsm_x4(bf, fsb + (FKb + (p * 16 + lrow) * 72 + ks * 16 + gh * 8) * 2);
                uint32_t b0[2] = { bf[0], bf[2] }, b1[2] = { bf[1], bf[3] };
                mma_f16acc(sh[2*p],   qf[ks], b0);
                mma_f16acc(sh[2*p+1], qf[ks], b1);
            }
        }

        // unpack to fp32 for softmax
        float s[16][4];
        #pragma unroll
        for (int nt = 0; nt < 16; nt++) {
            float2 f01 = __half22float2(*reinterpret_cast<__half2*>(&sh[nt][0]));
            float2 f23 = __half22float2(*reinterpret_cast<__half2*>(&sh[nt][1]));
            s[nt][0] = f01.x; s[nt][1] = f01.y;
            s[nt][2] = f23.x; s[nt][3] = f23.y;
        }

        // ---- causal mask (diagonal tile) ----
        if (kt == qt) {
            int r0 = rowA, r1 = rowA + 8;
            #pragma unroll
            for (int nt = 0; nt < 16; nt++) {
                #pragma unroll
                for (int e = 0; e < 2; e++) {
                    int col = nt * 8 + 2 * qc + e;
                    if (col > r0) s[nt][e]     = -1e30f;
                    if (col > r1) s[nt][2 + e] = -1e30f;
                }
            }
        }

        // ---- online softmax (P stays in registers) ----
        float tm0 = -1e30f, tm1 = -1e30f;
        #pragma unroll
        for (int nt = 0; nt < 16; nt++) {
            tm0 = fmaxf(tm0, fmaxf(s[nt][0], s[nt][1]));
            tm1 = fmaxf(tm1, fmaxf(s[nt][2], s[nt][3]));
        }
        tm0 = fmaxf(tm0, __shfl_xor_sync(0xffffffffu, tm0, 1));
        tm0 = fmaxf(tm0, __shfl_xor_sync(0xffffffffu, tm0, 2));
        tm1 = fmaxf(tm1, __shfl_xor_sync(0xffffffffu, tm1, 1));
        tm1 = fmaxf(tm1, __shfl_xor_sync(0xffffffffu, tm1, 2));

        float mn0 = fmaxf(m[0], tm0), mn1 = fmaxf(m[1], tm1);
        float c0 = __expf(m[0] - mn0), c1 = __expf(m[1] - mn1);
        m[0] = mn0; m[1] = mn1;

        float sum0 = 0.f, sum1 = 0.f;
        uint32_t pfr[16][2];
        #pragma unroll
        for (int nt = 0; nt < 16; nt++) {
            float p0 = __expf(s[nt][0] - mn0);
            float p1 = __expf(s[nt][1] - mn0);
            float p2 = __expf(s[nt][2] - mn1);
            float p3 = __expf(s[nt][3] - mn1);
            sum0 += p0 + p1; sum1 += p2 + p3;
            __half2 h01 = __floats2half2_rn(p0, p1);
            __half2 h23 = __floats2half2_rn(p2, p3);
            pfr[nt][0] = *reinterpret_cast<uint32_t*>(&h01);
            pfr[nt][1] = *reinterpret_cast<uint32_t*>(&h23);
        }
        sum0 += __shfl_xor_sync(0xffffffffu, sum0, 1);
        sum0 += __shfl_xor_sync(0xffffffffu, sum0, 2);
        sum1 += __shfl_xor_sync(0xffffffffu, sum1, 1);
        sum1 += __shfl_xor_sync(0xffffffffu, sum1, 2);
        l[0] = l[0] * c0 + sum0;
        l[1] = l[1] * c1 + sum1;

        #pragma unroll
        for (int nt = 0; nt < 8; nt++) {
            o[nt][0] *= c0; o[nt][1] *= c0;
            o[nt][2] *= c1; o[nt][3] *= c1;
        }

        // ---- O += P @ V (fp32 accumulate; V via ldmatrix.trans) ----
        #pragma unroll
        for (int ks = 0; ks < 8; ks++) {
            uint32_t af[4] = { pfr[2*ks][0], pfr[2*ks][1],
                               pfr[2*ks+1][0], pfr[2*ks+1][1] };
            #pragma unroll
            for (int p = 0; p < 4; p++) {
                uint32_t bf[4];
                ldsm_x4_t(bf, fsb + (FVb + (ks * 16 + kr) * 72 + p * 16 + dof) * 2);
                uint32_t b0[2] = { bf[0], bf[2] }, b1[2] = { bf[1], bf[3] };
                mma_f16(o[2*p],   af, b0);
                mma_f16(o[2*p+1], af, b1);
            }
        }
    }

    // ---- epilogue: O /= l, write fp16 [B,T,C] ----
    int b = bh >> 4, h = bh & 15;
    int t0 = qt * 128 + rowA;
    float inv0 = 1.f / l[0], inv1 = 1.f / l[1];
    #pragma unroll
    for (int nt = 0; nt < 8; nt++) {
        int col = h * 64 + nt * 8 + 2 * qc;
        *reinterpret_cast<__half2*>(&g_attnh[((size_t)(b * T_ + t0)) * C_ + col]) =
            __floats2half2_rn(o[nt][0] * inv0, o[nt][1] * inv0);
        *reinterpret_cast<__half2*>(&g_attnh[((size_t)(b * T_ + t0 + 8)) * C_ + col]) =
            __floats2half2_rn(o[nt][2] * inv1, o[nt][3] * inv1);
    }
}

// ================= LayerNorm (fp32 in -> fp16 out) =================
__global__ void __launch_bounds__(256) ln_kernel(const float* __restrict__ x,
                                                 const float* __restrict__ g,
                                                 const float* __restrict__ beta,
                                                 __half* __restrict__ out)
{
    int row = blockIdx.x, tid = threadIdx.x;
    float4 v = reinterpret_cast<const float4*>(x + (size_t)row * C_)[tid];
    float s  = v.x + v.y + v.z + v.w;
    float ss = v.x*v.x + v.y*v.y + v.z*v.z + v.w*v.w;
    __shared__ float shs[8], shss[8];
    #pragma unroll
    for (int o = 16; o; o >>= 1) {
        s  += __shfl_xor_sync(0xffffffffu, s,  o);
        ss += __shfl_xor_sync(0xffffffffu, ss, o);
    }
    if ((tid & 31) == 0) { shs[tid >> 5] = s; shss[tid >> 5] = ss; }
    __syncthreads();
    if (tid < 32) {
        float s2  = (tid < 8) ? shs[tid]  : 0.f;
        float ss2 = (tid < 8) ? shss[tid] : 0.f;
        #pragma unroll
        for (int o = 4; o; o >>= 1) {
            s2  += __shfl_xor_sync(0xffffffffu, s2,  o);
            ss2 += __shfl_xor_sync(0xffffffffu, ss2, o);
        }
        if (tid == 0) { shs[0] = s2; shss[0] = ss2; }
    }
    __syncthreads();
    float mean = shs[0] * (1.f / C_);
    float var  = shss[0] * (1.f / C_) - mean * mean;
    float inv  = rsqrtf(var + EPS_);
    float4 gg = reinterpret_cast<const float4*>(g)[tid];
    float4 bb = reinterpret_cast<const float4*>(beta)[tid];
    __half2 h0 = __floats2half2_rn(gg.x * (v.x - mean) * inv + bb.x,
                                   gg.y * (v.y - mean) * inv + bb.y);
    __half2 h1 = __floats2half2_rn(gg.z * (v.z - mean) * inv + bb.z,
                                   gg.w * (v.w - mean) * inv + bb.w);
    uint2 pk = { *(uint32_t*)&h0, *(uint32_t*)&h1 };
    reinterpret_cast<uint2*>(out + (size_t)row * C_)[tid] = pk;
}

// ================= launch =================
extern "C" void kernel_launch(void* const* d_in, const int* in_sizes, int n_in,
                              void* d_out, int out_size)
{
    const float* x     = (const float*)d_in[0];
    const float* Wq    = (const float*)d_in[1];
    const float* Wk    = (const float*)d_in[2];
    const float* Wv    = (const float*)d_in[3];
    const float* Wproj = (const float*)d_in[4];
    const float* bproj = (const float*)d_in[5];
    const float* W1    = (const float*)d_in[6];
    const float* b1    = (const float*)d_in[7];
    const float* W2    = (const float*)d_in[8];
    const float* b2    = (const float*)d_in[9];
    const float* g1    = (const float*)d_in[10];
    const float* beta1 = (const float*)d_in[11];
    const float* g2    = (const float*)d_in[12];
    const float* beta2 = (const float*)d_in[13];
    float* out = (float*)d_out;

    __half *xnh, *qkvh, *attnh, *h1h, *wqkvh, *wpth, *w1th, *w2th;
    float  *x1;
    cudaGetSymbolAddress((void**)&xnh,   g_xnh);
    cudaGetSymbolAddress((void**)&qkvh,  g_qkvh);
    cudaGetSymbolAddress((void**)&attnh, g_attnh);
    cudaGetSymbolAddress((void**)&h1h,   g_h1h);
    cudaGetSymbolAddress((void**)&x1,    g_x1);
    cudaGetSymbolAddress((void**)&wqkvh, g_wqkvh);
    cudaGetSymbolAddress((void**)&wpth,  g_wpth);
    cudaGetSymbolAddress((void**)&w1th,  g_w1th);
    cudaGetSymbolAddress((void**)&w2th,  g_w2th);

    cudaFuncSetAttribute(mma_gemm<EPI_QKV>,   cudaFuncAttributeMaxDynamicSharedMemorySize, SMEM_SZ);
    cudaFuncSetAttribute(mma_gemm<EPI_PROJ>,  cudaFuncAttributeMaxDynamicSharedMemorySize, SMEM_SZ);
    cudaFuncSetAttribute(mma_gemm<EPI_RELU>,  cudaFuncAttributeMaxDynamicSharedMemorySize, SMEM_SZ);
    cudaFuncSetAttribute(mma_gemm<EPI_RESID>, cudaFuncAttributeMaxDynamicSharedMemorySize, SMEM_SZ);
    cudaFuncSetAttribute(flash_kernel,        cudaFuncAttributeMaxDynamicSharedMemorySize, FA_SMEM);

    // 8 launches total
    ln_kernel<<<M_, 256>>>(x, g1, beta1, xnh);                                    // 0
    convert_weights_kernel<<<dim3(32, 32, 6), dim3(32, 8)>>>(Wproj, W1, W2, Wq, Wk, Wv);  // 1
    mma_gemm<EPI_QKV><<<dim3(3 * C_ / 128, M_ / 128), 256, SMEM_SZ>>>(xnh, wqkvh, nullptr, nullptr, qkvh);  // 2
    flash_kernel<<<dim3(T_ / 128, B_ * H_), 256, FA_SMEM>>>();                    // 3
    mma_gemm<EPI_PROJ><<<dim3(C_ / 128, M_ / 128), 256, SMEM_SZ>>>(attnh, wpth, bproj, x, x1);  // 4
    ln_kernel<<<M_, 256>>>(x1, g2, beta2, xnh);                                   // 5
    mma_gemm<EPI_RELU><<<dim3(C_ / 128, M_ / 128), 256, SMEM_SZ>>>(xnh, w1th, b1, nullptr, h1h);   // 6
    mma_gemm<EPI_RESID><<<dim3(C_ / 128, M_ / 128), 256, SMEM_SZ>>>(h1h, w2th, b2, x1, out);       // 7
}

// round 10
// speedup vs baseline: 1.1028x; 1.0103x over previous
#include <cuda_runtime.h>
#include <cuda_fp16.h>
#include <math.h>
#include <cstdint>

#define B_   8
#define T_   1024
#define C_   1024
#define H_   16
#define DH   64
#define M_   (B_*T_)
#define KDIM 1024
#define EPS_ 1e-5f

// ---------------- scratch (device globals) ----------------
__device__ __half g_xnh  [M_*C_];
__device__ __half g_qkvh [3ll*M_*C_];      // q,k,v all [B,H,T,Dh] (q pre-scaled)
__device__ __half g_attnh[M_*C_];
__device__ __half g_h1h  [M_*C_];
__device__ float  g_x1   [M_*C_];
__device__ __half g_wqkvh[3ll*C_*C_];      // [N=3072][K=1024]
__device__ __half g_wpth [C_*C_];
__device__ __half g_w1th [C_*C_];
__device__ __half g_w2th [C_*C_];

// ================= helpers =================
__device__ __forceinline__ uint32_t smem_u32(const void* p) {
    uint32_t a;
    asm("{ .reg .u64 t; cvta.to.shared.u64 t, %1; cvt.u32.u64 %0, t; }" : "=r"(a) : "l"(p));
    return a;
}
__device__ __forceinline__ void cp_async16(uint32_t dst, const void* src) {
    asm volatile("cp.async.cg.shared.global [%0], [%1], 16;" :: "r"(dst), "l"(src));
}
#define CP_COMMIT() asm volatile("cp.async.commit_group;" ::: "memory")
#define CP_WAIT(n)  asm volatile("cp.async.wait_group %0;" :: "n"(n) : "memory")

__device__ __forceinline__ void mma_f16(float* d, const uint32_t* a, const uint32_t* b) {
    asm volatile(
        "mma.sync.aligned.m16n8k16.row.col.f32.f16.f16.f32 "
        "{%0,%1,%2,%3}, {%4,%5,%6,%7}, {%8,%9}, {%0,%1,%2,%3};"
        : "+f"(d[0]), "+f"(d[1]), "+f"(d[2]), "+f"(d[3])
        : "r"(a[0]), "r"(a[1]), "r"(a[2]), "r"(a[3]), "r"(b[0]), "r"(b[1]));
}
// f16 accumulate variant (2x rate; used only for flash S with K=64 reduction)
__device__ __forceinline__ void mma_f16acc(uint32_t* d, const uint32_t* a, const uint32_t* b) {
    asm volatile(
        "mma.sync.aligned.m16n8k16.row.col.f16.f16.f16.f16 "
        "{%0,%1}, {%2,%3,%4,%5}, {%6,%7}, {%0,%1};"
        : "+r"(d[0]), "+r"(d[1])
        : "r"(a[0]), "r"(a[1]), "r"(a[2]), "r"(a[3]), "r"(b[0]), "r"(b[1]));
}
__device__ __forceinline__ void ldsm_x4(uint32_t* r, uint32_t addr) {
    asm volatile("ldmatrix.sync.aligned.m8n8.x4.shared.b16 {%0,%1,%2,%3}, [%4];"
        : "=r"(r[0]), "=r"(r[1]), "=r"(r[2]), "=r"(r[3]) : "r"(addr));
}
__device__ __forceinline__ void ldsm_x4_t(uint32_t* r, uint32_t addr) {
    asm volatile("ldmatrix.sync.aligned.m8n8.x4.trans.shared.b16 {%0,%1,%2,%3}, [%4];"
        : "=r"(r[0]), "=r"(r[1]), "=r"(r[2]), "=r"(r[3]) : "r"(addr));
}

// ================= fused weight conversion (6 matrices, ONE launch) ============
__global__ void __launch_bounds__(256) convert_weights_kernel(
    const float* __restrict__ Wp, const float* __restrict__ W1, const float* __restrict__ W2,
    const float* __restrict__ Wq, const float* __restrict__ Wk, const float* __restrict__ Wv)
{
    __shared__ float tile[32][33];
    int tx = threadIdx.x, ty = threadIdx.y;
    int z = blockIdx.z;
    if (z < 3) {
        const float* in = (z == 0) ? Wp : (z == 1) ? W1 : W2;
        __half* out = (z == 0) ? g_wpth : (z == 1) ? g_w1th : g_w2th;
        int n0 = blockIdx.x * 32, k0 = blockIdx.y * 32;
        #pragma unroll
        for (int i = 0; i < 32; i += 8)
            tile[ty + i][tx] = in[(size_t)(k0 + ty + i) * C_ + n0 + tx];
        __syncthreads();
        #pragma unroll
        for (int i = 0; i < 32; i += 8)
            out[(size_t)(n0 + ty + i) * KDIM + k0 + tx] = __float2half_rn(tile[tx][ty + i]);
    } else {
        const float* in = (z == 3) ? Wq : (z == 4) ? Wk : Wv;
        __half* out = g_wqkvh + (size_t)(z - 3) * C_ * C_;
        int h = blockIdx.x >> 1, d0 = (blockIdx.x & 1) * 32, c0 = blockIdx.y * 32;
        #pragma unroll
        for (int i = 0; i < 32; i += 8)
            tile[ty + i][tx] = in[(size_t)h * (C_ * DH) + (size_t)(c0 + ty + i) * DH + d0 + tx];
        __syncthreads();
        #pragma unroll
        for (int i = 0; i < 32; i += 8)
            out[(size_t)(h * DH + d0 + ty + i) * KDIM + c0 + tx] = __float2half_rn(tile[tx][ty + i]);
    }
}

// ================= fp16 GEMM: 128x128 tile, 256 thr, BK=64h, 3-stage, ldmatrix ====
enum { EPI_QKV = 0, EPI_PROJ = 1, EPI_RELU = 2, EPI_RESID = 3 };

#define BKH 64
#define NCHUNK (KDIM / BKH)                // 16
#define A_H (128*BKH)                      // 8192 halves
#define STG_H (2*A_H)                      // 16384 halves (32KB)
#define SMEM_SZ (3 * STG_H * 2)            // 96KB

__device__ __forceinline__ int hidx(int row, int grp, int off) {
    return row * 64 + ((grp ^ (row & 7)) << 3) + off;
}

template<int EPI>
__global__ void __launch_bounds__(256) mma_gemm(
    const __half* __restrict__ A,      // [M][1024]
    const __half* __restrict__ Bt,     // [Ntot][1024]
    const float*  __restrict__ bias,
    const float*  __restrict__ resid,
    void*         __restrict__ outv)
{
    extern __shared__ __half sm[];
    int tid = threadIdx.x, wid = tid >> 5, lane = tid & 31;
    int warpM = wid & 3, warpN = wid >> 2;      // 4 x 2 warps
    int qrow = lane >> 2, qc = lane & 3;
    int lrow = lane & 15, gh = lane >> 4;
    int mBase = blockIdx.y * 128, nBase = blockIdx.x * 128;

    const __half* aSrc = A  + (size_t)mBase * KDIM;
    const __half* bSrc = Bt + (size_t)nBase * KDIM;

    auto load_stage = [&](int c, int s) {
        __half* dA = sm + s * STG_H;
        __half* dB = dA + A_H;
        #pragma unroll
        for (int i = 0; i < 4; i++) {
            int id = tid + i * 256, r = id >> 3, g = id & 7;
            cp_async16(smem_u32(dA + hidx(r, g, 0)),
                       aSrc + (size_t)r * KDIM + c * BKH + g * 8);
            cp_async16(smem_u32(dB + hidx(r, g, 0)),
                       bSrc + (size_t)r * KDIM + c * BKH + g * 8);
        }
    };

    int rA[2], rB[4];
    rA[0] = warpM * 32 + lrow;  rA[1] = rA[0] + 16;
    #pragma unroll
    for (int p = 0; p < 4; p++) rB[p] = warpN * 64 + p * 16 + lrow;

    float acc[2][8][4];
    #pragma unroll
    for (int mt = 0; mt < 2; mt++)
        #pragma unroll
        for (int nt = 0; nt < 8; nt++)
            #pragma unroll
            for (int r = 0; r < 4; r++) acc[mt][nt][r] = 0.f;

    load_stage(0, 0); CP_COMMIT();
    load_stage(1, 1); CP_COMMIT();

    uint32_t smBase = smem_u32(sm);

    #pragma unroll 1
    for (int c = 0; c < NCHUNK; c++) {
        if (c < NCHUNK - 2) { CP_WAIT(1); } else { CP_WAIT(0); }
        __syncthreads();
        if (c + 2 < NCHUNK) { load_stage(c + 2, (c + 2) % 3); CP_COMMIT(); }

        uint32_t baseA = smBase + (c % 3) * (STG_H * 2);
        uint32_t baseB = baseA + A_H * 2;

        #pragma unroll
        for (int ks = 0; ks < 4; ks++) {
            int grp = 2 * ks + gh;
            uint32_t af[2][4];
            ldsm_x4(af[0], baseA + (rA[0] * 64 + ((grp ^ (rA[0] & 7)) << 3)) * 2);
            ldsm_x4(af[1], baseA + (rA[1] * 64 + ((grp ^ (rA[1] & 7)) << 3)) * 2);
            #pragma unroll
            for (int p = 0; p < 4; p++) {
                uint32_t bf[4];
                ldsm_x4(bf, baseB + (rB[p] * 64 + ((grp ^ (rB[p] & 7)) << 3)) * 2);
                uint32_t b0[2] = { bf[0], bf[2] }, b1[2] = { bf[1], bf[3] };
                mma_f16(acc[0][2*p],   af[0], b0);
                mma_f16(acc[1][2*p],   af[1], b0);
                mma_f16(acc[0][2*p+1], af[0], b1);
                mma_f16(acc[1][2*p+1], af[1], b1);
            }
        }
    }

    // ---- epilogue ----
    #pragma unroll
    for (int mt = 0; mt < 2; mt++) {
        #pragma unroll
        for (int r = 0; r < 2; r++) {
            int m = mBase + warpM * 32 + mt * 16 + qrow + r * 8;
            #pragma unroll
            for (int nt = 0; nt < 8; nt++) {
                int col = nBase + warpN * 64 + nt * 8 + qc * 2;
                float vx = acc[mt][nt][r * 2], vy = acc[mt][nt][r * 2 + 1];
                if (EPI == EPI_QKV) {
                    __half* out = (__half*)outv;
                    int which = col >> 10, nn = col & 1023;
                    int h = nn >> 6, d = nn & 63;
                    int b = m >> 10, t = m & 1023;
                    float sc = (which == 0) ? 0.125f : 1.f;   // q pre-scaled by Dh^-0.5
                    *reinterpret_cast<__half2*>(
                        &out[(size_t)which * (M_ * C_) +
                             (((size_t)(b * H_ + h) * T_ + t) * DH + d)]) =
                        __floats2half2_rn(vx * sc, vy * sc);
                } else if (EPI == EPI_RELU) {
                    __half* out = (__half*)outv;
                    size_t idx = (size_t)m * C_ + col;
                    float ox = fmaxf(vx + bias[col], 0.f);
                    float oy = fmaxf(vy + bias[col + 1], 0.f);
                    *reinterpret_cast<__half2*>(&out[idx]) = __floats2half2_rn(ox, oy);
                } else {
                    float* out = (float*)outv;
                    size_t idx = (size_t)m * C_ + col;
                    float2 rs = *reinterpret_cast<const float2*>(&resid[idx]);
                    float2 o = { vx + bias[col] + rs.x, vy + bias[col + 1] + rs.y };
                    *reinterpret_cast<float2*>(&out[idx]) = o;
                }
            }
        }
    }
}

// ====== fused flash attention: register-P (in-place), f16-acc S, 2 CTA/SM ======
#define FQ  0
#define FK0 9216
#define FK1 18432
#define FV0 27648
#define FV1 36864
#define FA_SMEM (46080 * 2)                // 92160 bytes; x2 CTA = 184KB < 228KB

__global__ void __launch_bounds__(256, 2) flash_kernel()
{
    extern __shared__ __half fs[];
    int tid = threadIdx.x, wid = tid >> 5, lane = tid & 31;
    int qrow = lane >> 2, qc = lane & 3;
    int lrow = lane & 15, gh = lane >> 4;
    int kr  = (lane & 7) | ((lane & 16) >> 1);   // trans-ldsm key row
    int dof = lane & 8;                          // trans-ldsm dim offset
    int qt = gridDim.x - 1 - blockIdx.x;
    int bh = blockIdx.y;

    const __half* Q = g_qkvh + ((size_t)bh * T_ + qt * 128) * DH;
    const __half* K = g_qkvh + (size_t)M_ * C_  + (size_t)bh * T_ * DH;
    const __half* V = g_qkvh + 2ll * M_ * C_    + (size_t)bh * T_ * DH;

    auto ldtile = [&](int dst, const __half* src) {
        #pragma unroll
        for (int i = 0; i < 4; i++) {
            int id = tid + i * 256;
            int row = id >> 3, j = id & 7;
            cp_async16(smem_u32(fs + dst + row * 72 + j * 8), src + row * 64 + j * 8);
        }
    };

    ldtile(FQ, Q);
    ldtile(FK0, K);
    ldtile(FV0, V);
    CP_COMMIT();

    int rowA = wid * 16 + qrow;
    int lmRow = wid * 16 + lrow;
    uint32_t fsb = smem_u32(fs);

    float m[2] = { -1e30f, -1e30f }, l[2] = { 0.f, 0.f };
    float o[8][4];
    #pragma unroll
    for (int nt = 0; nt < 8; nt++)
        #pragma unroll
        for (int r = 0; r < 4; r++) o[nt][r] = 0.f;

    uint32_t qf[4][4];

    #pragma unroll 1
    for (int kt = 0; kt <= qt; kt++) {
        __syncthreads();
        if (kt + 1 <= qt) {
            ldtile((kt & 1) ? FK0 : FK1, K + (size_t)(kt + 1) * 128 * DH);
            ldtile((kt & 1) ? FV0 : FV1, V + (size_t)(kt + 1) * 128 * DH);
            CP_COMMIT();
            CP_WAIT(1);
        } else {
            CP_WAIT(0);
        }
        __syncthreads();

        int FKb = (kt & 1) ? FK1 : FK0;
        int FVb = (kt & 1) ? FV1 : FV0;

        if (kt == 0) {
            #pragma unroll
            for (int ks = 0; ks < 4; ks++)
                ldsm_x4(qf[ks], fsb + (FQ + lmRow * 72 + ks * 16 + gh * 8) * 2);
        }

        // ---- S = Q K^T, fp16 accumulate; sh holds packed half2 scores ----
        uint32_t sh[16][2];
        #pragma unroll
        for (int nt = 0; nt < 16; nt++) { sh[nt][0] = 0u; sh[nt][1] = 0u; }

        #pragma unroll
        for (int ks = 0; ks < 4; ks++) {
            #pragma unroll
            for (int p = 0; p < 8; p++) {
                uint32_t bf[4];
                ldsm_x4(bf, fsb + (FKb + (p * 16 + lrow) * 72 + ks * 16 + gh * 8) * 2);
                uint32_t b0[2] = { bf[0], bf[2] }, b1[2] = { bf[1], bf[3] };
                mma_f16acc(sh[2*p],   qf[ks], b0);
                mma_f16acc(sh[2*p+1], qf[ks], b1);
            }
        }

        // ---- causal mask in half domain (diagonal tile only) ----
        if (kt == qt) {
            int r0 = rowA, r1 = rowA + 8;
            #pragma unroll
            for (int nt = 0; nt < 16; nt++) {
                float2 f01 = __half22float2(*reinterpret_cast<__half2*>(&sh[nt][0]));
                float2 f23 = __half22float2(*reinterpret_cast<__half2*>(&sh[nt][1]));
                int c0i = nt * 8 + 2 * qc, c1i = c0i + 1;
                if (c0i > r0) f01.x = -1e30f;
                if (c1i > r0) f01.y = -1e30f;
                if (c0i > r1) f23.x = -1e30f;
                if (c1i > r1) f23.y = -1e30f;
                __half2 h01 = __floats2half2_rn(f01.x, f01.y);   // saturates to -inf
                __half2 h23 = __floats2half2_rn(f23.x, f23.y);
                sh[nt][0] = *reinterpret_cast<uint32_t*>(&h01);
                sh[nt][1] = *reinterpret_cast<uint32_t*>(&h23);
            }
        }

        // ---- pass 1: row max (unpack on the fly; no fp32 S array) ----
        float tm0 = -1e30f, tm1 = -1e30f;
        #pragma unroll
        for (int nt = 0; nt < 16; nt++) {
            float2 f01 = __half22float2(*reinterpret_cast<__half2*>(&sh[nt][0]));
            float2 f23 = __half22float2(*reinterpret_cast<__half2*>(&sh[nt][1]));
            tm0 = fmaxf(tm0, fmaxf(f01.x, f01.y));
            tm1 = fmaxf(tm1, fmaxf(f23.x, f23.y));
        }
        tm0 = fmaxf(tm0, __shfl_xor_sync(0xffffffffu, tm0, 1));
        tm0 = fmaxf(tm0, __shfl_xor_sync(0xffffffffu, tm0, 2));
        tm1 = fmaxf(tm1, __shfl_xor_sync(0xffffffffu, tm1, 1));
        tm1 = fmaxf(tm1, __shfl_xor_sync(0xffffffffu, tm1, 2));

        float mn0 = fmaxf(m[0], tm0), mn1 = fmaxf(m[1], tm1);
        float c0 = __expf(m[0] - mn0), c1 = __expf(m[1] - mn1);
        m[0] = mn0; m[1] = mn1;

        // ---- pass 2: exp + sum, overwrite sh with packed P (A-fragment layout) ----
        float sum0 = 0.f, sum1 = 0.f;
        #pragma unroll
        for (int nt = 0; nt < 16; nt++) {
            float2 f01 = __half22float2(*reinterpret_cast<__half2*>(&sh[nt][0]));
            float2 f23 = __half22float2(*reinterpret_cast<__half2*>(&sh[nt][1]));
            float p0 = __expf(f01.x - mn0);
            float p1 = __expf(f01.y - mn0);
            float p2 = __expf(f23.x - mn1);
            float p3 = __expf(f23.y - mn1);
            sum0 += p0 + p1; sum1 += p2 + p3;
            __half2 h01 = __floats2half2_rn(p0, p1);
            __half2 h23 = __floats2half2_rn(p2, p3);
            sh[nt][0] = *reinterpret_cast<uint32_t*>(&h01);
            sh[nt][1] = *reinterpret_cast<uint32_t*>(&h23);
        }
        sum0 += __shfl_xor_sync(0xffffffffu, sum0, 1);
        sum0 += __shfl_xor_sync(0xffffffffu, sum0, 2);
        sum1 += __shfl_xor_sync(0xffffffffu, sum1, 1);
        sum1 += __shfl_xor_sync(0xffffffffu, sum1, 2);
        l[0] = l[0] * c0 + sum0;
        l[1] = l[1] * c1 + sum1;

        #pragma unroll
        for (int nt = 0; nt < 8; nt++) {
            o[nt][0] *= c0; o[nt][1] *= c0;
            o[nt][2] *= c1; o[nt][3] *= c1;
        }

        // ---- O += P @ V (fp32 accumulate; P from sh registers; V via ldmatrix.trans) --
        #pragma unroll
        for (int ks = 0; ks < 8; ks++) {
            uint32_t af[4] = { sh[2*ks][0], sh[2*ks][1],
                               sh[2*ks+1][0], sh[2*ks+1][1] };
            #pragma unroll
            for (int p = 0; p < 4; p++) {
                uint32_t bf[4];
                ldsm_x4_t(bf, fsb + (FVb + (ks * 16 + kr) * 72 + p * 16 + dof) * 2);
                uint32_t b0[2] = { bf[0], bf[2] }, b1[2] = { bf[1], bf[3] };
                mma_f16(o[2*p],   af, b0);
                mma_f16(o[2*p+1], af, b1);
            }
        }
    }

    // ---- epilogue: O /= l, write fp16 [B,T,C] ----
    int b = bh >> 4, h = bh & 15;
    int t0 = qt * 128 + rowA;
    float inv0 = 1.f / l[0], inv1 = 1.f / l[1];
    #pragma unroll
    for (int nt = 0; nt < 8; nt++) {
        int col = h * 64 + nt * 8 + 2 * qc;
        *reinterpret_cast<__half2*>(&g_attnh[((size_t)(b * T_ + t0)) * C_ + col]) =
            __floats2half2_rn(o[nt][0] * inv0, o[nt][1] * inv0);
        *reinterpret_cast<__half2*>(&g_attnh[((size_t)(b * T_ + t0 + 8)) * C_ + col]) =
            __floats2half2_rn(o[nt][2] * inv1, o[nt][3] * inv1);
    }
}

// ================= LayerNorm (fp32 in -> fp16 out) =================
__global__ void __launch_bounds__(256) ln_kernel(const float* __restrict__ x,
                                                 const float* __restrict__ g,
                                                 const float* __restrict__ beta,
                                                 __half* __restrict__ out)
{
    int row = blockIdx.x, tid = threadIdx.x;
    float4 v = reinterpret_cast<const float4*>(x + (size_t)row * C_)[tid];
    float s  = v.x + v.y + v.z + v.w;
    float ss = v.x*v.x + v.y*v.y + v.z*v.z + v.w*v.w;
    __shared__ float shs[8], shss[8];
    #pragma unroll
    for (int o = 16; o; o >>= 1) {
        s  += __shfl_xor_sync(0xffffffffu, s,  o);
        ss += __shfl_xor_sync(0xffffffffu, ss, o);
    }
    if ((tid & 31) == 0) { shs[tid >> 5] = s; shss[tid >> 5] = ss; }
    __syncthreads();
    if (tid < 32) {
        float s2  = (tid < 8) ? shs[tid]  : 0.f;
        float ss2 = (tid < 8) ? shss[tid] : 0.f;
        #pragma unroll
        for (int o = 4; o; o >>= 1) {
            s2  += __shfl_xor_sync(0xffffffffu, s2,  o);
            ss2 += __shfl_xor_sync(0xffffffffu, ss2, o);
        }
        if (tid == 0) { shs[0] = s2; shss[0] = ss2; }
    }
    __syncthreads();
    float mean = shs[0] * (1.f / C_);
    float var  = shss[0] * (1.f / C_) - mean * mean;
    float inv  = rsqrtf(var + EPS_);
    float4 gg = reinterpret_cast<const float4*>(g)[tid];
    float4 bb = reinterpret_cast<const float4*>(beta)[tid];
    __half2 h0 = __floats2half2_rn(gg.x * (v.x - mean) * inv + bb.x,
                                   gg.y * (v.y - mean) * inv + bb.y);
    __half2 h1 = __floats2half2_rn(gg.z * (v.z - mean) * inv + bb.z,
                                   gg.w * (v.w - mean) * inv + bb.w);
    uint2 pk = { *(uint32_t*)&h0, *(uint32_t*)&h1 };
    reinterpret_cast<uint2*>(out + (size_t)row * C_)[tid] = pk;
}

// ================= launch =================
extern "C" void kernel_launch(void* const* d_in, const int* in_sizes, int n_in,
                              void* d_out, int out_size)
{
    const float* x     = (const float*)d_in[0];
    const float* Wq    = (const float*)d_in[1];
    const float* Wk    = (const float*)d_in[2];
    const float* Wv    = (const float*)d_in[3];
    const float* Wproj = (const float*)d_in[4];
    const float* bproj = (const float*)d_in[5];
    const float* W1    = (const float*)d_in[6];
    const float* b1    = (const float*)d_in[7];
    const float* W2    = (const float*)d_in[8];
    const float* b2    = (const float*)d_in[9];
    const float* g1    = (const float*)d_in[10];
    const float* beta1 = (const float*)d_in[11];
    const float* g2    = (const float*)d_in[12];
    const float* beta2 = (const float*)d_in[13];
    float* out = (float*)d_out;

    __half *xnh, *qkvh, *attnh, *h1h, *wqkvh, *wpth, *w1th, *w2th;
    float  *x1;
    cudaGetSymbolAddress((void**)&xnh,   g_xnh);
    cudaGetSymbolAddress((void**)&qkvh,  g_qkvh);
    cudaGetSymbolAddress((void**)&attnh, g_attnh);
    cudaGetSymbolAddress((void**)&h1h,   g_h1h);
    cudaGetSymbolAddress((void**)&x1,    g_x1);
    cudaGetSymbolAddress((void**)&wqkvh, g_wqkvh);
    cudaGetSymbolAddress((void**)&wpth,  g_wpth);
    cudaGetSymbolAddress((void**)&w1th,  g_w1th);
    cudaGetSymbolAddress((void**)&w2th,  g_w2th);

    cudaFuncSetAttribute(mma_gemm<EPI_QKV>,   cudaFuncAttributeMaxDynamicSharedMemorySize, SMEM_SZ);
    cudaFuncSetAttribute(mma_gemm<EPI_PROJ>,  cudaFuncAttributeMaxDynamicSharedMemorySize, SMEM_SZ);
    cudaFuncSetAttribute(mma_gemm<EPI_RELU>,  cudaFuncAttributeMaxDynamicSharedMemorySize, SMEM_SZ);
    cudaFuncSetAttribute(mma_gemm<EPI_RESID>, cudaFuncAttributeMaxDynamicSharedMemorySize, SMEM_SZ);
    cudaFuncSetAttribute(flash_kernel,        cudaFuncAttributeMaxDynamicSharedMemorySize, FA_SMEM);

    // 8 launches total
    ln_kernel<<<M_, 256>>>(x, g1, beta1, xnh);                                    // 0
    convert_weights_kernel<<<dim3(32, 32, 6), dim3(32, 8)>>>(Wproj, W1, W2, Wq, Wk, Wv);  // 1
    mma_gemm<EPI_QKV><<<dim3(3 * C_ / 128, M_ / 128), 256, SMEM_SZ>>>(xnh, wqkvh, nullptr, nullptr, qkvh);  // 2
    flash_kernel<<<dim3(T_ / 128, B_ * H_), 256, FA_SMEM>>>();                    // 3
    mma_gemm<EPI_PROJ><<<dim3(C_ / 128, M_ / 128), 256, SMEM_SZ>>>(attnh, wpth, bproj, x, x1);  // 4
    ln_kernel<<<M_, 256>>>(x1, g2, beta2, xnh);                                   // 5
    mma_gemm<EPI_RELU><<<dim3(C_ / 128, M_ / 128), 256, SMEM_SZ>>>(xnh, w1th, b1, nullptr, h1h);   // 6
    mma_gemm<EPI_RESID><<<dim3(C_ / 128, M_ / 128), 256, SMEM_SZ>>>(h1h, w2th, b2, x1, out);       // 7
}

// round 11
// speedup vs baseline: 1.1354x; 1.0296x over previous
#include <cuda_runtime.h>
#include <cuda_fp16.h>
#include <math.h>
#include <cstdint>

#define B_   8
#define T_   1024
#define C_   1024
#define H_   16
#define DH   64
#define M_   (B_*T_)
#define KDIM 1024
#define EPS_ 1e-5f
#define QSCALE 0.1803368801111204f   // Dh^-0.5 * log2(e)

// ---------------- scratch (device globals) ----------------
__device__ __half g_xnh  [M_*C_];
__device__ __half g_qkvh [3ll*M_*C_];      // q,k,v all [B,H,T,Dh] (q pre-scaled, log2 domain)
__device__ __half g_attnh[M_*C_];
__device__ __half g_h1h  [M_*C_];
__device__ float  g_x1   [M_*C_];
__device__ __half g_wqkvh[3ll*C_*C_];      // [N=3072][K=1024]
__device__ __half g_wpth [C_*C_];
__device__ __half g_w1th [C_*C_];
__device__ __half g_w2th [C_*C_];

// ================= helpers =================
__device__ __forceinline__ uint32_t smem_u32(const void* p) {
    uint32_t a;
    asm("{ .reg .u64 t; cvta.to.shared.u64 t, %1; cvt.u32.u64 %0, t; }" : "=r"(a) : "l"(p));
    return a;
}
__device__ __forceinline__ void cp_async16(uint32_t dst, const void* src) {
    asm volatile("cp.async.cg.shared.global [%0], [%1], 16;" :: "r"(dst), "l"(src));
}
#define CP_COMMIT() asm volatile("cp.async.commit_group;" ::: "memory")
#define CP_WAIT(n)  asm volatile("cp.async.wait_group %0;" :: "n"(n) : "memory")

__device__ __forceinline__ void mma_f16(float* d, const uint32_t* a, const uint32_t* b) {
    asm volatile(
        "mma.sync.aligned.m16n8k16.row.col.f32.f16.f16.f32 "
        "{%0,%1,%2,%3}, {%4,%5,%6,%7}, {%8,%9}, {%0,%1,%2,%3};"
        : "+f"(d[0]), "+f"(d[1]), "+f"(d[2]), "+f"(d[3])
        : "r"(a[0]), "r"(a[1]), "r"(a[2]), "r"(a[3]), "r"(b[0]), "r"(b[1]));
}
// f16 accumulate variant (2x rate; flash S only, K=64 reduction)
__device__ __forceinline__ void mma_f16acc(uint32_t* d, const uint32_t* a, const uint32_t* b) {
    asm volatile(
        "mma.sync.aligned.m16n8k16.row.col.f16.f16.f16.f16 "
        "{%0,%1}, {%2,%3,%4,%5}, {%6,%7}, {%0,%1};"
        : "+r"(d[0]), "+r"(d[1])
        : "r"(a[0]), "r"(a[1]), "r"(a[2]), "r"(a[3]), "r"(b[0]), "r"(b[1]));
}
__device__ __forceinline__ void ldsm_x4(uint32_t* r, uint32_t addr) {
    asm volatile("ldmatrix.sync.aligned.m8n8.x4.shared.b16 {%0,%1,%2,%3}, [%4];"
        : "=r"(r[0]), "=r"(r[1]), "=r"(r[2]), "=r"(r[3]) : "r"(addr));
}
__device__ __forceinline__ void ldsm_x4_t(uint32_t* r, uint32_t addr) {
    asm volatile("ldmatrix.sync.aligned.m8n8.x4.trans.shared.b16 {%0,%1,%2,%3}, [%4];"
        : "=r"(r[0]), "=r"(r[1]), "=r"(r[2]), "=r"(r[3]) : "r"(addr));
}

// ================= fused weight conversion (6 matrices, ONE launch) ============
__global__ void __launch_bounds__(256) convert_weights_kernel(
    const float* __restrict__ Wp, const float* __restrict__ W1, const float* __restrict__ W2,
    const float* __restrict__ Wq, const float* __restrict__ Wk, const float* __restrict__ Wv)
{
    __shared__ float tile[32][33];
    int tx = threadIdx.x, ty = threadIdx.y;
    int z = blockIdx.z;
    if (z < 3) {
        const float* in = (z == 0) ? Wp : (z == 1) ? W1 : W2;
        __half* out = (z == 0) ? g_wpth : (z == 1) ? g_w1th : g_w2th;
        int n0 = blockIdx.x * 32, k0 = blockIdx.y * 32;
        #pragma unroll
        for (int i = 0; i < 32; i += 8)
            tile[ty + i][tx] = in[(size_t)(k0 + ty + i) * C_ + n0 + tx];
        __syncthreads();
        #pragma unroll
        for (int i = 0; i < 32; i += 8)
            out[(size_t)(n0 + ty + i) * KDIM + k0 + tx] = __float2half_rn(tile[tx][ty + i]);
    } else {
        const float* in = (z == 3) ? Wq : (z == 4) ? Wk : Wv;
        __half* out = g_wqkvh + (size_t)(z - 3) * C_ * C_;
        int h = blockIdx.x >> 1, d0 = (blockIdx.x & 1) * 32, c0 = blockIdx.y * 32;
        #pragma unroll
        for (int i = 0; i < 32; i += 8)
            tile[ty + i][tx] = in[(size_t)h * (C_ * DH) + (size_t)(c0 + ty + i) * DH + d0 + tx];
        __syncthreads();
        #pragma unroll
        for (int i = 0; i < 32; i += 8)
            out[(size_t)(h * DH + d0 + ty + i) * KDIM + c0 + tx] = __float2half_rn(tile[tx][ty + i]);
    }
}

// ================= fp16 GEMM: 128x128 tile, 256 thr, BK=64h, 3-stage, ldmatrix ====
enum { EPI_QKV = 0, EPI_PROJ = 1, EPI_RELU = 2, EPI_RESID = 3 };

#define BKH 64
#define NCHUNK (KDIM / BKH)                // 16
#define A_H (128*BKH)                      // 8192 halves
#define STG_H (2*A_H)                      // 16384 halves (32KB)
#define SMEM_SZ (3 * STG_H * 2)            // 96KB

__device__ __forceinline__ int hidx(int row, int grp, int off) {
    return row * 64 + ((grp ^ (row & 7)) << 3) + off;
}

template<int EPI>
__global__ void __launch_bounds__(256) mma_gemm(
    const __half* __restrict__ A,      // [M][1024]
    const __half* __restrict__ Bt,     // [Ntot][1024]
    const float*  __restrict__ bias,
    const float*  __restrict__ resid,
    void*         __restrict__ outv)
{
    extern __shared__ __half sm[];
    int tid = threadIdx.x, wid = tid >> 5, lane = tid & 31;
    int warpM = wid & 3, warpN = wid >> 2;      // 4 x 2 warps
    int qrow = lane >> 2, qc = lane & 3;
    int lrow = lane & 15, gh = lane >> 4;
    int mBase = blockIdx.y * 128, nBase = blockIdx.x * 128;

    const __half* aSrc = A  + (size_t)mBase * KDIM;
    const __half* bSrc = Bt + (size_t)nBase * KDIM;

    auto load_stage = [&](int c, int s) {
        __half* dA = sm + s * STG_H;
        __half* dB = dA + A_H;
        #pragma unroll
        for (int i = 0; i < 4; i++) {
            int id = tid + i * 256, r = id >> 3, g = id & 7;
            cp_async16(smem_u32(dA + hidx(r, g, 0)),
                       aSrc + (size_t)r * KDIM + c * BKH + g * 8);
            cp_async16(smem_u32(dB + hidx(r, g, 0)),
                       bSrc + (size_t)r * KDIM + c * BKH + g * 8);
        }
    };

    int rA[2], rB[4];
    rA[0] = warpM * 32 + lrow;  rA[1] = rA[0] + 16;
    #pragma unroll
    for (int p = 0; p < 4; p++) rB[p] = warpN * 64 + p * 16 + lrow;

    float acc[2][8][4];
    #pragma unroll
    for (int mt = 0; mt < 2; mt++)
        #pragma unroll
        for (int nt = 0; nt < 8; nt++)
            #pragma unroll
            for (int r = 0; r < 4; r++) acc[mt][nt][r] = 0.f;

    load_stage(0, 0); CP_COMMIT();
    load_stage(1, 1); CP_COMMIT();

    uint32_t smBase = smem_u32(sm);

    #pragma unroll 1
    for (int c = 0; c < NCHUNK; c++) {
        if (c < NCHUNK - 2) { CP_WAIT(1); } else { CP_WAIT(0); }
        __syncthreads();
        if (c + 2 < NCHUNK) { load_stage(c + 2, (c + 2) % 3); CP_COMMIT(); }

        uint32_t baseA = smBase + (c % 3) * (STG_H * 2);
        uint32_t baseB = baseA + A_H * 2;

        #pragma unroll
        for (int ks = 0; ks < 4; ks++) {
            int grp = 2 * ks + gh;
            uint32_t af[2][4];
            ldsm_x4(af[0], baseA + (rA[0] * 64 + ((grp ^ (rA[0] & 7)) << 3)) * 2);
            ldsm_x4(af[1], baseA + (rA[1] * 64 + ((grp ^ (rA[1] & 7)) << 3)) * 2);
            #pragma unroll
            for (int p = 0; p < 4; p++) {
                uint32_t bf[4];
                ldsm_x4(bf, baseB + (rB[p] * 64 + ((grp ^ (rB[p] & 7)) << 3)) * 2);
                uint32_t b0[2] = { bf[0], bf[2] }, b1[2] = { bf[1], bf[3] };
                mma_f16(acc[0][2*p],   af[0], b0);
                mma_f16(acc[1][2*p],   af[1], b0);
                mma_f16(acc[0][2*p+1], af[0], b1);
                mma_f16(acc[1][2*p+1], af[1], b1);
            }
        }
    }

    // ---- epilogue ----
    #pragma unroll
    for (int mt = 0; mt < 2; mt++) {
        #pragma unroll
        for (int r = 0; r < 2; r++) {
            int m = mBase + warpM * 32 + mt * 16 + qrow + r * 8;
            #pragma unroll
            for (int nt = 0; nt < 8; nt++) {
                int col = nBase + warpN * 64 + nt * 8 + qc * 2;
                float vx = acc[mt][nt][r * 2], vy = acc[mt][nt][r * 2 + 1];
                if (EPI == EPI_QKV) {
                    __half* out = (__half*)outv;
                    int which = col >> 10, nn = col & 1023;
                    int h = nn >> 6, d = nn & 63;
                    int b = m >> 10, t = m & 1023;
                    // q pre-scaled by Dh^-0.5 * log2(e)  (flash works in exp2 domain)
                    float sc = (which == 0) ? QSCALE : 1.f;
                    *reinterpret_cast<__half2*>(
                        &out[(size_t)which * (M_ * C_) +
                             (((size_t)(b * H_ + h) * T_ + t) * DH + d)]) =
                        __floats2half2_rn(vx * sc, vy * sc);
                } else if (EPI == EPI_RELU) {
                    __half* out = (__half*)outv;
                    size_t idx = (size_t)m * C_ + col;
                    float ox = fmaxf(vx + bias[col], 0.f);
                    float oy = fmaxf(vy + bias[col + 1], 0.f);
                    *reinterpret_cast<__half2*>(&out[idx]) = __floats2half2_rn(ox, oy);
                } else {
                    float* out = (float*)outv;
                    size_t idx = (size_t)m * C_ + col;
                    float2 rs = *reinterpret_cast<const float2*>(&resid[idx]);
                    float2 o = { vx + bias[col] + rs.x, vy + bias[col + 1] + rs.y };
                    *reinterpret_cast<float2*>(&out[idx]) = o;
                }
            }
        }
    }
}

// ====== fused flash attention: half-domain softmax, rowsum-by-MMA, 2 CTA/SM ======
#define FQ  0
#define FK0 9216
#define FK1 18432
#define FV0 27648
#define FV1 36864
#define FA_SMEM (46080 * 2)                // 92160 bytes; x2 CTA = 184KB < 228KB

__global__ void __launch_bounds__(256, 2) flash_kernel()
{
    extern __shared__ __half fs[];
    int tid = threadIdx.x, wid = tid >> 5, lane = tid & 31;
    int qrow = lane >> 2, qc = lane & 3;
    int lrow = lane & 15, gh = lane >> 4;
    int kr  = (lane & 7) | ((lane & 16) >> 1);   // trans-ldsm key row
    int dof = lane & 8;                          // trans-ldsm dim offset
    int qt = gridDim.x - 1 - blockIdx.x;
    int bh = blockIdx.y;

    const __half* Q = g_qkvh + ((size_t)bh * T_ + qt * 128) * DH;
    const __half* K = g_qkvh + (size_t)M_ * C_  + (size_t)bh * T_ * DH;
    const __half* V = g_qkvh + 2ll * M_ * C_    + (size_t)bh * T_ * DH;

    auto ldtile = [&](int dst, const __half* src) {
        #pragma unroll
        for (int i = 0; i < 4; i++) {
            int id = tid + i * 256;
            int row = id >> 3, j = id & 7;
            cp_async16(smem_u32(fs + dst + row * 72 + j * 8), src + row * 64 + j * 8);
        }
    };

    ldtile(FQ, Q);
    ldtile(FK0, K);
    ldtile(FV0, V);
    CP_COMMIT();

    int rowA = wid * 16 + qrow;
    int lmRow = wid * 16 + lrow;
    uint32_t fsb = smem_u32(fs);

    float m[2] = { -1e30f, -1e30f }, l[2] = { 0.f, 0.f };
    float o[8][4];
    #pragma unroll
    for (int nt = 0; nt < 8; nt++)
        #pragma unroll
        for (int r = 0; r < 4; r++) o[nt][r] = 0.f;

    uint32_t qf[4][4];
    const uint32_t onesb[2] = { 0x3C003C00u, 0x3C003C00u };   // half2(1,1) x2

    #pragma unroll 1
    for (int kt = 0; kt <= qt; kt++) {
        __syncthreads();
        if (kt + 1 <= qt) {
            ldtile((kt & 1) ? FK0 : FK1, K + (size_t)(kt + 1) * 128 * DH);
            ldtile((kt & 1) ? FV0 : FV1, V + (size_t)(kt + 1) * 128 * DH);
            CP_COMMIT();
            CP_WAIT(1);
        } else {
            CP_WAIT(0);
        }
        __syncthreads();

        int FKb = (kt & 1) ? FK1 : FK0;
        int FVb = (kt & 1) ? FV1 : FV0;

        if (kt == 0) {
            #pragma unroll
            for (int ks = 0; ks < 4; ks++)
                ldsm_x4(qf[ks], fsb + (FQ + lmRow * 72 + ks * 16 + gh * 8) * 2);
        }

        // ---- S' = (Q*log2e*scale) K^T, fp16 accumulate; packed half2 ----
        uint32_t sh[16][2];
        #pragma unroll
        for (int nt = 0; nt < 16; nt++) { sh[nt][0] = 0u; sh[nt][1] = 0u; }

        #pragma unroll
        for (int ks = 0; ks < 4; ks++) {
            #pragma unroll
            for (int p = 0; p < 8; p++) {
                uint32_t bf[4];
                ldsm_x4(bf, fsb + (FKb + (p * 16 + lrow) * 72 + ks * 16 + gh * 8) * 2);
                uint32_t b0[2] = { bf[0], bf[2] }, b1[2] = { bf[1], bf[3] };
                mma_f16acc(sh[2*p],   qf[ks], b0);
                mma_f16acc(sh[2*p+1], qf[ks], b1);
            }
        }

        // ---- causal mask (diagonal tile only): set to -inf in half ----
        if (kt == qt) {
            int r0 = rowA, r1 = rowA + 8;
            #pragma unroll
            for (int nt = 0; nt < 16; nt++) {
                __half2* h01 = reinterpret_cast<__half2*>(&sh[nt][0]);
                __half2* h23 = reinterpret_cast<__half2*>(&sh[nt][1]);
                int c0i = nt * 8 + 2 * qc, c1i = c0i + 1;
                const __half ninf = __ushort_as_half(0xFC00);
                if (c0i > r0) h01->x = ninf;
                if (c1i > r0) h01->y = ninf;
                if (c0i > r1) h23->x = ninf;
                if (c1i > r1) h23->y = ninf;
            }
        }

        // ---- pass 1: row max via hmax2 chains (packed domain) ----
        __half2 mx0 = __halves2half2(__ushort_as_half(0xFC00), __ushort_as_half(0xFC00));
        __half2 mx1 = mx0;
        #pragma unroll
        for (int nt = 0; nt < 16; nt++) {
            mx0 = __hmax2(mx0, *reinterpret_cast<__half2*>(&sh[nt][0]));
            mx1 = __hmax2(mx1, *reinterpret_cast<__half2*>(&sh[nt][1]));
        }
        float tm0 = fmaxf(__low2float(mx0), __high2float(mx0));
        float tm1 = fmaxf(__low2float(mx1), __high2float(mx1));
        tm0 = fmaxf(tm0, __shfl_xor_sync(0xffffffffu, tm0, 1));
        tm0 = fmaxf(tm0, __shfl_xor_sync(0xffffffffu, tm0, 2));
        tm1 = fmaxf(tm1, __shfl_xor_sync(0xffffffffu, tm1, 1));
        tm1 = fmaxf(tm1, __shfl_xor_sync(0xffffffffu, tm1, 2));

        float mn0 = fmaxf(m[0], tm0), mn1 = fmaxf(m[1], tm1);
        float c0 = exp2f(m[0] - mn0), c1 = exp2f(m[1] - mn1);
        m[0] = mn0; m[1] = mn1;

        // ---- pass 2: P = 2^(S'-m) entirely in half (hsub2 + ex2.approx.f16x2) ----
        __half2 mn0h = __float2half2_rn(mn0), mn1h = __float2half2_rn(mn1);
        #pragma unroll
        for (int nt = 0; nt < 16; nt++) {
            __half2 p01 = h2exp2(__hsub2(*reinterpret_cast<__half2*>(&sh[nt][0]), mn0h));
            __half2 p23 = h2exp2(__hsub2(*reinterpret_cast<__half2*>(&sh[nt][1]), mn1h));
            sh[nt][0] = *reinterpret_cast<uint32_t*>(&p01);
            sh[nt][1] = *reinterpret_cast<uint32_t*>(&p23);
        }

        // ---- row sum via MMA with ones-B (fp32 exact, includes quad reduce) ----
        float ls[4] = { 0.f, 0.f, 0.f, 0.f };
        #pragma unroll
        for (int ks = 0; ks < 8; ks++) {
            uint32_t af[4] = { sh[2*ks][0], sh[2*ks][1],
                               sh[2*ks+1][0], sh[2*ks+1][1] };
            mma_f16(ls, af, onesb);
        }
        l[0] = l[0] * c0 + ls[0];
        l[1] = l[1] * c1 + ls[2];

        #pragma unroll
        for (int nt = 0; nt < 8; nt++) {
            o[nt][0] *= c0; o[nt][1] *= c0;
            o[nt][2] *= c1; o[nt][3] *= c1;
        }

        // ---- O += P @ V (fp32 accumulate; P in registers; V via ldmatrix.trans) ----
        #pragma unroll
        for (int ks = 0; ks < 8; ks++) {
            uint32_t af[4] = { sh[2*ks][0], sh[2*ks][1],
                               sh[2*ks+1][0], sh[2*ks+1][1] };
            #pragma unroll
            for (int p = 0; p < 4; p++) {
                uint32_t bf[4];
                ldsm_x4_t(bf, fsb + (FVb + (ks * 16 + kr) * 72 + p * 16 + dof) * 2);
                uint32_t b0[2] = { bf[0], bf[2] }, b1[2] = { bf[1], bf[3] };
                mma_f16(o[2*p],   af, b0);
                mma_f16(o[2*p+1], af, b1);
            }
        }
    }

    // ---- epilogue: O /= l, write fp16 [B,T,C] ----
    int b = bh >> 4, h = bh & 15;
    int t0 = qt * 128 + rowA;
    float inv0 = 1.f / l[0], inv1 = 1.f / l[1];
    #pragma unroll
    for (int nt = 0; nt < 8; nt++) {
        int col = h * 64 + nt * 8 + 2 * qc;
        *reinterpret_cast<__half2*>(&g_attnh[((size_t)(b * T_ + t0)) * C_ + col]) =
            __floats2half2_rn(o[nt][0] * inv0, o[nt][1] * inv0);
        *reinterpret_cast<__half2*>(&g_attnh[((size_t)(b * T_ + t0 + 8)) * C_ + col]) =
            __floats2half2_rn(o[nt][2] * inv1, o[nt][3] * inv1);
    }
}

// ================= LayerNorm (fp32 in -> fp16 out) =================
__global__ void __launch_bounds__(256) ln_kernel(const float* __restrict__ x,
                                                 const float* __restrict__ g,
                                                 const float* __restrict__ beta,
                                                 __half* __restrict__ out)
{
    int row = blockIdx.x, tid = threadIdx.x;
    float4 v = reinterpret_cast<const float4*>(x + (size_t)row * C_)[tid];
    float s  = v.x + v.y + v.z + v.w;
    float ss = v.x*v.x + v.y*v.y + v.z*v.z + v.w*v.w;
    __shared__ float shs[8], shss[8];
    #pragma unroll
    for (int o = 16; o; o >>= 1) {
        s  += __shfl_xor_sync(0xffffffffu, s,  o);
        ss += __shfl_xor_sync(0xffffffffu, ss, o);
    }
    if ((tid & 31) == 0) { shs[tid >> 5] = s; shss[tid >> 5] = ss; }
    __syncthreads();
    if (tid < 32) {
        float s2  = (tid < 8) ? shs[tid]  : 0.f;
        float ss2 = (tid < 8) ? shss[tid] : 0.f;
        #pragma unroll
        for (int o = 4; o; o >>= 1) {
            s2  += __shfl_xor_sync(0xffffffffu, s2,  o);
            ss2 += __shfl_xor_sync(0xffffffffu, ss2, o);
        }
        if (tid == 0) { shs[0] = s2; shss[0] = ss2; }
    }
    __syncthreads();
    float mean = shs[0] * (1.f / C_);
    float var  = shss[0] * (1.f / C_) - mean * mean;
    float inv  = rsqrtf(var + EPS_);
    float4 gg = reinterpret_cast<const float4*>(g)[tid];
    float4 bb = reinterpret_cast<const float4*>(beta)[tid];
    __half2 h0 = __floats2half2_rn(gg.x * (v.x - mean) * inv + bb.x,
                                   gg.y * (v.y - mean) * inv + bb.y);
    __half2 h1 = __floats2half2_rn(gg.z * (v.z - mean) * inv + bb.z,
                                   gg.w * (v.w - mean) * inv + bb.w);
    uint2 pk = { *(uint32_t*)&h0, *(uint32_t*)&h1 };
    reinterpret_cast<uint2*>(out + (size_t)row * C_)[tid] = pk;
}

// ================= launch =================
extern "C" void kernel_launch(void* const* d_in, const int* in_sizes, int n_in,
                              void* d_out, int out_size)
{
    const float* x     = (const float*)d_in[0];
    const float* Wq    = (const float*)d_in[1];
    const float* Wk    = (const float*)d_in[2];
    const float* Wv    = (const float*)d_in[3];
    const float* Wproj = (const float*)d_in[4];
    const float* bproj = (const float*)d_in[5];
    const float* W1    = (const float*)d_in[6];
    const float* b1    = (const float*)d_in[7];
    const float* W2    = (const float*)d_in[8];
    const float* b2    = (const float*)d_in[9];
    const float* g1    = (const float*)d_in[10];
    const float* beta1 = (const float*)d_in[11];
    const float* g2    = (const float*)d_in[12];
    const float* beta2 = (const float*)d_in[13];
    float* out = (float*)d_out;

    __half *xnh, *qkvh, *attnh, *h1h, *wqkvh, *wpth, *w1th, *w2th;
    float  *x1;
    cudaGetSymbolAddress((void**)&xnh,   g_xnh);
    cudaGetSymbolAddress((void**)&qkvh,  g_qkvh);
    cudaGetSymbolAddress((void**)&attnh, g_attnh);
    cudaGetSymbolAddress((void**)&h1h,   g_h1h);
    cudaGetSymbolAddress((void**)&x1,    g_x1);
    cudaGetSymbolAddress((void**)&wqkvh, g_wqkvh);
    cudaGetSymbolAddress((void**)&wpth,  g_wpth);
    cudaGetSymbolAddress((void**)&w1th,  g_w1th);
    cudaGetSymbolAddress((void**)&w2th,  g_w2th);

    cudaFuncSetAttribute(mma_gemm<EPI_QKV>,   cudaFuncAttributeMaxDynamicSharedMemorySize, SMEM_SZ);
    cudaFuncSetAttribute(mma_gemm<EPI_PROJ>,  cudaFuncAttributeMaxDynamicSharedMemorySize, SMEM_SZ);
    cudaFuncSetAttribute(mma_gemm<EPI_RELU>,  cudaFuncAttributeMaxDynamicSharedMemorySize, SMEM_SZ);
    cudaFuncSetAttribute(mma_gemm<EPI_RESID>, cudaFuncAttributeMaxDynamicSharedMemorySize, SMEM_SZ);
    cudaFuncSetAttribute(flash_kernel,        cudaFuncAttributeMaxDynamicSharedMemorySize, FA_SMEM);

    // 8 launches total
    ln_kernel<<<M_, 256>>>(x, g1, beta1, xnh);                                    // 0
    convert_weights_kernel<<<dim3(32, 32, 6), dim3(32, 8)>>>(Wproj, W1, W2, Wq, Wk, Wv);  // 1
    mma_gemm<EPI_QKV><<<dim3(3 * C_ / 128, M_ / 128), 256, SMEM_SZ>>>(xnh, wqkvh, nullptr, nullptr, qkvh);  // 2
    flash_kernel<<<dim3(T_ / 128, B_ * H_), 256, FA_SMEM>>>();                    // 3
    mma_gemm<EPI_PROJ><<<dim3(C_ / 128, M_ / 128), 256, SMEM_SZ>>>(attnh, wpth, bproj, x, x1);  // 4
    ln_kernel<<<M_, 256>>>(x1, g2, beta2, xnh);                                   // 5
    mma_gemm<EPI_RELU><<<dim3(C_ / 128, M_ / 128), 256, SMEM_SZ>>>(xnh, w1th, b1, nullptr, h1h);   // 6
    mma_gemm<EPI_RESID><<<dim3(C_ / 128, M_ / 128), 256, SMEM_SZ>>>(h1h, w2th, b2, x1, out);       // 7
}